// round 4
// baseline (speedup 1.0000x reference)
#include <cuda_runtime.h>
#include <math.h>

#define NB   32
#define TE   512
#define LD   128
#define VV   8000
#define HH   1024
#define KSZ  128
#define G1   4096
#define G2   512
#define KT   1152
#define NBLK 128

__device__ float g_X[(LD*NB)*256];
__device__ float g_Xg[(LD*NB)*G1];
__device__ float g_act[NB*KT];          // [0:128)=ctx, [128:1152)=h1
__device__ float g_h2[NB*KSZ];
__device__ float g_c1[NB*HH];
__device__ float g_c2[NB*KSZ];
__device__ float g_part1[4*NB*G1];
__device__ float g_part2[16*NB*G2];
__device__ float g_h2ctx[(LD*NB)*256];
__device__ unsigned g_arrive = 0;
__device__ unsigned g_gen = 0;

__device__ __forceinline__ float sigm(float x){ return 1.0f/(1.0f + expf(-x)); }
__device__ __forceinline__ unsigned ldv(const unsigned* p){
    unsigned v; asm volatile("ld.volatile.global.u32 %0, [%1];" : "=r"(v) : "l"(p)); return v; }
__device__ __forceinline__ void stv(unsigned* p, unsigned v){
    asm volatile("st.volatile.global.u32 [%0], %1;" :: "l"(p), "r"(v)); }

__device__ __forceinline__ void gbar()
{
    __syncthreads();
    if (threadIdx.x == 0) {
        __threadfence();
        unsigned gen = ldv(&g_gen);
        if (atomicAdd(&g_arrive, 1u) == NBLK - 1u) {
            stv(&g_arrive, 0u);
            __threadfence();
            stv(&g_gen, gen + 1u);
        } else {
            while (ldv(&g_gen) == gen) __nanosleep(64);
        }
        __threadfence();   // CCTL.IVALL -> drop stale L1
    }
    __syncthreads();
}

// ---------------- init ----------------
__global__ __launch_bounds__(256) void kInit(const int* __restrict__ text,
                                             const float* __restrict__ emb,
                                             const float* __restrict__ values)
{
    int b = blockIdx.x, tid = threadIdx.x;
    if (b < LD*NB) {
        int t = b >> 5, n = b & 31;
        int idx = (t == 0) ? 1 : text[n*LD + (t-1)];
        g_X[b*256 + tid] = emb[idx*256 + tid];
    } else {
        int i = (b - LD*NB)*256 + tid;
        if (i < 32768) { g_c1[i] = 0.f; }
        else if (i < 65536) { int u = i - 32768; int n = u >> 10, uu = u & 1023; g_act[n*KT + 128 + uu] = 0.f; }
        else if (i < 69632) { g_c2[i - 65536] = 0.f; }
        else if (i < 73728) { g_h2[i - 69632] = 0.f; }
        else if (i < 77824) { int u = i - 73728; int n = u >> 7, k = u & 127;
                              g_act[n*KT + k] = values[n*(TE*128) + k]; }
    }
}

// ---------------- big GEMM (unchanged, known correct) ----------------
template<int LDB, int MODE>
__global__ __launch_bounds__(256) void kGemmBig(const float* __restrict__ A,
                                                const float* __restrict__ B,
                                                const float* __restrict__ bias1,
                                                const float* __restrict__ bias2,
                                                float* __restrict__ C, int Nc)
{
    __shared__ float As[16][132];
    __shared__ float Bs[16][68];
    int tid = threadIdx.x;
    int m_base = blockIdx.y * 128;
    int n_base = blockIdx.x * 64;
    int tm = tid & 15, tn = tid >> 4;
    int m0 = tm*8, n0 = tn*4;
    float acc[8][4];
#pragma unroll
    for (int i=0;i<8;i++)
#pragma unroll
        for (int j=0;j<4;j++) acc[i][j]=0.f;
    int a_row = tid >> 1, a_kq = (tid & 1)*8;
    int b_row = tid >> 2, b_kq = (tid & 3)*4;
    for (int kc = 0; kc < 256; kc += 16) {
        float4 a0 = *(const float4*)&A[(m_base + a_row)*256 + kc + a_kq];
        float4 a1 = *(const float4*)&A[(m_base + a_row)*256 + kc + a_kq + 4];
        float4 b0 = *(const float4*)&B[(n_base + b_row)*LDB + kc + b_kq];
        __syncthreads();
        As[a_kq+0][a_row]=a0.x; As[a_kq+1][a_row]=a0.y; As[a_kq+2][a_row]=a0.z; As[a_kq+3][a_row]=a0.w;
        As[a_kq+4][a_row]=a1.x; As[a_kq+5][a_row]=a1.y; As[a_kq+6][a_row]=a1.z; As[a_kq+7][a_row]=a1.w;
        Bs[b_kq+0][b_row]=b0.x; Bs[b_kq+1][b_row]=b0.y; Bs[b_kq+2][b_row]=b0.z; Bs[b_kq+3][b_row]=b0.w;
        __syncthreads();
#pragma unroll
        for (int kk = 0; kk < 16; kk++) {
            float4 av0 = *(const float4*)&As[kk][m0];
            float4 av1 = *(const float4*)&As[kk][m0+4];
            float4 bv  = *(const float4*)&Bs[kk][n0];
            float a8[8] = {av0.x,av0.y,av0.z,av0.w,av1.x,av1.y,av1.z,av1.w};
            float b4[4] = {bv.x,bv.y,bv.z,bv.w};
#pragma unroll
            for (int i=0;i<8;i++)
#pragma unroll
                for (int j=0;j<4;j++) acc[i][j] = fmaf(a8[i], b4[j], acc[i][j]);
        }
    }
    float bb[4];
#pragma unroll
    for (int j=0;j<4;j++) {
        int gj = n_base + n0 + j;
        bb[j] = bias1[gj] + (MODE==0 ? bias2[gj] : 0.f);
    }
#pragma unroll
    for (int i=0;i<8;i++) {
        int r = m_base + m0 + i;
        float4 v = make_float4(acc[i][0]+bb[0], acc[i][1]+bb[1], acc[i][2]+bb[2], acc[i][3]+bb[3]);
        if (MODE == 0) *(float4*)&C[r*Nc + n_base + n0] = v;
        else { int n = r & 31, t = r >> 5; *(float4*)&C[(n*LD + t)*Nc + n_base + n0] = v; }
    }
}

// ---------------- persistent decoder ----------------
__global__ __launch_bounds__(256) void kPersist(
    const float* __restrict__ key, const float* __restrict__ values,
    const int* __restrict__ elens,
    const float* __restrict__ W_ih1, const float* __restrict__ W_hh1,
    const float* __restrict__ W_ih2, const float* __restrict__ W_hh2,
    const float* __restrict__ b_ih2, const float* __restrict__ b_hh2)
{
    __shared__ float sA[16][36];
    __shared__ float sW[16][132];
    __shared__ float h2s[128];
    __shared__ float es[512];
    __shared__ float red[256];
    __shared__ float cs[2][128];

    int bid = blockIdx.x, tid = threadIdx.x;

    for (int t = 0; t < LD; t++) {
        // ===== Phase 1: LSTM1 split-K GEMM (bid -> jb, s) =====
        {
            int jb = (bid & 31) * 128;
            int s  = bid >> 5;
            int k_start = s * 288;
            int tm = tid & 7, tn = tid >> 3;
            int m0 = tm*4, n0 = tn*4;
            float acc[4][4];
#pragma unroll
            for (int i=0;i<4;i++)
#pragma unroll
                for (int j=0;j<4;j++) acc[i][j]=0.f;
            int an = tid >> 3, ak = (tid & 7)*2;
            int wj = tid >> 1, wkg = (tid & 1)*8;
            for (int kc = k_start; kc < k_start + 288; kc += 16) {
                float2 av = *(const float2*)&g_act[an*KT + kc + ak];
                int kg0 = kc + wkg;
                float4 w0, w1;
                if (kg0 < 128) {
                    const float* p = &W_ih1[(jb+wj)*384 + 256 + kg0];
                    w0 = *(const float4*)p; w1 = *(const float4*)(p+4);
                } else {
                    const float* p = &W_hh1[(jb+wj)*1024 + (kg0-128)];
                    w0 = *(const float4*)p; w1 = *(const float4*)(p+4);
                }
                __syncthreads();
                sA[ak][an]   = av.x;
                sA[ak+1][an] = av.y;
                sW[wkg+0][wj]=w0.x; sW[wkg+1][wj]=w0.y; sW[wkg+2][wj]=w0.z; sW[wkg+3][wj]=w0.w;
                sW[wkg+4][wj]=w1.x; sW[wkg+5][wj]=w1.y; sW[wkg+6][wj]=w1.z; sW[wkg+7][wj]=w1.w;
                __syncthreads();
#pragma unroll
                for (int kk = 0; kk < 16; kk++) {
                    float4 a4 = *(const float4*)&sA[kk][m0];
                    float4 b4 = *(const float4*)&sW[kk][n0];
                    float aa[4]={a4.x,a4.y,a4.z,a4.w};
                    float bv[4]={b4.x,b4.y,b4.z,b4.w};
#pragma unroll
                    for (int i=0;i<4;i++)
#pragma unroll
                        for (int j=0;j<4;j++) acc[i][j] = fmaf(aa[i], bv[j], acc[i][j]);
                }
            }
#pragma unroll
            for (int i=0;i<4;i++) {
                float4 v = make_float4(acc[i][0],acc[i][1],acc[i][2],acc[i][3]);
                *(float4*)&g_part1[(s*NB + m0 + i)*G1 + jb + n0] = v;
            }
        }
        gbar();

        // ===== Phase 2: cell1 =====
        {
            int id = bid*256 + tid;
            int n = id >> 10, u = id & 1023;
            const float* xg = &g_Xg[(t*NB + n)*G1];
            float gi = xg[u], gf = xg[u+1024], gg = xg[u+2048], go = xg[u+3072];
#pragma unroll
            for (int s=0;s<4;s++) {
                const float* p = &g_part1[(s*NB + n)*G1];
                gi += p[u]; gf += p[u+1024]; gg += p[u+2048]; go += p[u+3072];
            }
            float i_ = sigm(gi), f_ = sigm(gf), g_ = tanhf(gg), o_ = sigm(go);
            float c = f_*g_c1[id] + i_*g_;
            g_c1[id] = c;
            g_act[n*KT + 128 + u] = o_*tanhf(c);
        }
        gbar();

        // ===== Phase 3: LSTM2 split-K GEMM (threads duplicated via tid&127) =====
        {
            int td = tid & 127;
            int jb = (bid & 7) * 64;
            int s  = bid >> 3;
            int k0s = s * 72;
            int tm = td & 7, tn = td >> 3;
            int m0 = tm*4, n0 = tn*4;
            float acc[4][4];
#pragma unroll
            for (int i=0;i<4;i++)
#pragma unroll
                for (int j=0;j<4;j++) acc[i][j]=0.f;
            int an = td >> 2, ak = (td & 3)*2;
            int wj = td >> 1, wk = (td & 1)*4;
            for (int kc = k0s; kc < k0s + 72; kc += 8) {
                int ka = kc + ak;
                float2 av = (ka < 1024) ? *(const float2*)&g_act[an*KT + 128 + ka]
                                        : *(const float2*)&g_h2[an*KSZ + ka - 1024];
                int kw = kc + wk;
                float4 wv = (kw < 1024) ? *(const float4*)&W_ih2[(jb+wj)*1024 + kw]
                                        : *(const float4*)&W_hh2[(jb+wj)*128 + kw - 1024];
                __syncthreads();
                sA[ak][an]   = av.x;
                sA[ak+1][an] = av.y;
                sW[wk+0][wj]=wv.x; sW[wk+1][wj]=wv.y; sW[wk+2][wj]=wv.z; sW[wk+3][wj]=wv.w;
                __syncthreads();
#pragma unroll
                for (int kk = 0; kk < 8; kk++) {
                    float4 a4 = *(const float4*)&sA[kk][m0];
                    float4 b4 = *(const float4*)&sW[kk][n0];
                    float aa[4]={a4.x,a4.y,a4.z,a4.w};
                    float bv[4]={b4.x,b4.y,b4.z,b4.w};
#pragma unroll
                    for (int i=0;i<4;i++)
#pragma unroll
                        for (int j=0;j<4;j++) acc[i][j] = fmaf(aa[i], bv[j], acc[i][j]);
                }
            }
#pragma unroll
            for (int i=0;i<4;i++) {
                float4 v = make_float4(acc[i][0],acc[i][1],acc[i][2],acc[i][3]);
                *(float4*)&g_part2[(s*NB + m0 + i)*G2 + jb + n0] = v;
            }
        }
        gbar();

        // ===== Phase 4: cell2 + attention (blocks 0..31) =====
        if (bid < NB) {
            int n = bid;
            if (tid < 128) {
                int u = tid;
                float g4[4];
#pragma unroll
                for (int g = 0; g < 4; g++) {
                    int j = g*128 + u;
                    float a = b_ih2[j] + b_hh2[j];
#pragma unroll
                    for (int s = 0; s < 16; s++) a += g_part2[(s*NB + n)*G2 + j];
                    g4[g] = a;
                }
                float i_ = sigm(g4[0]), f_ = sigm(g4[1]), gg = tanhf(g4[2]), o_ = sigm(g4[3]);
                float c = f_*g_c2[n*KSZ + u] + i_*gg;
                g_c2[n*KSZ + u] = c;
                float h = o_*tanhf(c);
                h2s[u] = h;
                g_h2[n*KSZ + u] = h;
            }
            __syncthreads();
            int warp = tid >> 5, lane = tid & 31;
            int len = elens[n];
            float4 hv = ((const float4*)h2s)[lane];
            for (int te = warp; te < TE; te += 8) {
                const float4* kp = (const float4*)&key[(n*TE + te)*KSZ];
                float4 kv = kp[lane];
                float p = kv.x*hv.x + kv.y*hv.y + kv.z*hv.z + kv.w*hv.w;
                p += __shfl_xor_sync(0xffffffffu, p, 16);
                p += __shfl_xor_sync(0xffffffffu, p, 8);
                p += __shfl_xor_sync(0xffffffffu, p, 4);
                p += __shfl_xor_sync(0xffffffffu, p, 2);
                p += __shfl_xor_sync(0xffffffffu, p, 1);
                if (lane == 0) es[te] = (te >= len) ? -1.0e9f : p;
            }
            __syncthreads();
            float m = fmaxf(es[tid], es[tid + 256]);
            red[tid] = m;
            __syncthreads();
            for (int st = 128; st > 0; st >>= 1) {
                if (tid < st) red[tid] = fmaxf(red[tid], red[tid + st]);
                __syncthreads();
            }
            float mx = red[0];
            __syncthreads();
            float p0 = expf(es[tid] - mx);
            float p1 = expf(es[tid + 256] - mx);
            es[tid] = p0; es[tid + 256] = p1;
            red[tid] = p0 + p1;
            __syncthreads();
            for (int st = 128; st > 0; st >>= 1) {
                if (tid < st) red[tid] += red[tid + st];
                __syncthreads();
            }
            float inv = 1.0f / red[0];
            int v = tid & 127, half = tid >> 7;
            float acc = 0.f;
            int tb = half * 256;
#pragma unroll 4
            for (int te = tb; te < tb + 256; te++)
                acc += es[te] * values[(n*TE + te)*128 + v];
            cs[half][v] = acc;
            __syncthreads();
            if (tid < 128) {
                float ctx = (cs[0][tid] + cs[1][tid]) * inv;
                g_act[n*KT + tid] = ctx;
                float* hc = &g_h2ctx[(t*NB + n)*256];
                hc[tid]       = h2s[tid];
                hc[128 + tid] = ctx;
            }
        }
        if (t < LD-1) gbar();
    }
}

// ---------------- launch ----------------
extern "C" void kernel_launch(void* const* d_in, const int* in_sizes, int n_in,
                              void* d_out, int out_size)
{
    const float* key    = (const float*)d_in[0];
    const float* values = (const float*)d_in[1];
    const int*   elens  = (const int*)  d_in[2];
    const int*   text   = (const int*)  d_in[3];
    const float* emb    = (const float*)d_in[4];
    const float* W_ih1  = (const float*)d_in[5];
    const float* W_hh1  = (const float*)d_in[6];
    const float* b_ih1  = (const float*)d_in[7];
    const float* b_hh1  = (const float*)d_in[8];
    const float* W_ih2  = (const float*)d_in[9];
    const float* W_hh2  = (const float*)d_in[10];
    const float* b_ih2  = (const float*)d_in[11];
    const float* b_hh2  = (const float*)d_in[12];
    const float* W_out  = (const float*)d_in[13];
    const float* b_out  = (const float*)d_in[14];
    float* out = (float*)d_out;

    kInit<<<LD*NB + 304, 256>>>(text, emb, values);

    float* gXg; cudaGetSymbolAddress((void**)&gXg, g_Xg);
    float* gX;  cudaGetSymbolAddress((void**)&gX, g_X);
    kGemmBig<384,0><<<dim3(G1/64, (LD*NB)/128), 256>>>(gX, W_ih1, b_ih1, b_hh1, gXg, G1);

    kPersist<<<NBLK, 256>>>(key, values, elens, W_ih1, W_hh1, W_ih2, W_hh2, b_ih2, b_hh2);

    float* gHC; cudaGetSymbolAddress((void**)&gHC, g_h2ctx);
    kGemmBig<256,1><<<dim3(VV/64, (LD*NB)/128), 256>>>(gHC, W_out, b_out, (const float*)0, out, VV);
}

// round 7
// speedup vs baseline: 1.2115x; 1.2115x over previous
#include <cuda_runtime.h>
#include <math.h>

#define NB 32
#define TE 512
#define LD 128
#define VV 8000
#define HH 1024
#define KSZ 128
#define G1 4096
#define KT 1152
#define NBLK 128
typedef unsigned long long ull;

__device__ __align__(16) float g_X[(LD*NB)*256];
__device__ __align__(16) float g_Xg[(LD*NB)*G1];
__device__ __align__(16) float g_Xg2[(size_t)LD*G1*NB];
__device__ __align__(16) float g_Wt1[KT*G1];        // [k][j'], j'=u*4+g, j=g*1024+u
__device__ __align__(16) float g_Wt2[KT*512];       // [k][j'], j'=u*4+g, j=g*128+u
__device__ __align__(16) float g_A[KT*NB];          // [k][n]: k<128 ctx, k>=128 h1
__device__ __align__(16) float g_h2t[KSZ*NB];       // [k][n]
__device__ __align__(16) float g_c1[HH*NB];         // [u][n]
__device__ __align__(16) float g_c2[NB*KSZ];        // [n][u]
__device__ __align__(16) float g_p2[4*512*NB];      // [s][j'][n]
__device__ __align__(16) float g_h2ctx[(LD*NB)*256];
__device__ unsigned g_arrive = 0, g_gen = 0;

__device__ __forceinline__ float sigm(float x){ return 1.0f/(1.0f + expf(-x)); }
__device__ __forceinline__ unsigned ldv(const unsigned* p){
    unsigned v; asm volatile("ld.volatile.global.u32 %0, [%1];" : "=r"(v) : "l"(p)); return v; }
__device__ __forceinline__ void stv(unsigned* p, unsigned v){
    asm volatile("st.volatile.global.u32 [%0], %1;" :: "l"(p), "r"(v)); }

__device__ __forceinline__ void gbar()
{
    __syncthreads();
    if (threadIdx.x == 0) {
        __threadfence();
        unsigned gen = ldv(&g_gen);
        if (atomicAdd(&g_arrive, 1u) == NBLK - 1u) {
            stv(&g_arrive, 0u);
            __threadfence();
            stv(&g_gen, gen + 1u);
        } else {
            while (ldv(&g_gen) == gen) __nanosleep(32);
        }
        __threadfence();
    }
    __syncthreads();
}

__device__ __forceinline__ void fma2(ull& d, ull a, ull b){
    asm("fma.rn.f32x2 %0, %1, %2, %0;" : "+l"(d) : "l"(a), "l"(b));
}
__device__ __forceinline__ ull pack2(float x){
    ull d; unsigned u = __float_as_uint(x);
    asm("mov.b64 %0, {%1, %1};" : "=l"(d) : "r"(u));
    return d;
}

// ---------------- init ----------------
__global__ __launch_bounds__(256) void kInit(const int* __restrict__ text,
                                             const float* __restrict__ emb,
                                             const float* __restrict__ values)
{
    int b = blockIdx.x, tid = threadIdx.x;
    if (b < LD*NB) {
        int t = b >> 5, n = b & 31;
        int idx = (t == 0) ? 1 : text[n*LD + (t-1)];
        g_X[b*256 + tid] = emb[idx*256 + tid];
    } else {
        int i = (b - LD*NB)*256 + tid;
        if      (i < 32768) g_c1[i] = 0.f;
        else if (i < 65536) g_A[4096 + (i - 32768)] = 0.f;          // h1 rows
        else if (i < 69632) g_c2[i - 65536] = 0.f;
        else if (i < 73728) g_h2t[i - 69632] = 0.f;
        else if (i < 77824) { int u = i - 73728; int k = u >> 5, n = u & 31;
                              g_A[k*32 + n] = values[n*(TE*128) + k]; }
    }
}

// ---------------- weight repack to k-major ----------------
__global__ __launch_bounds__(256) void kPack(const float* __restrict__ W_ih1,
                                             const float* __restrict__ W_hh1,
                                             const float* __restrict__ W_ih2,
                                             const float* __restrict__ W_hh2)
{
    __shared__ float s[32][129];
    int b = blockIdx.x, tid = threadIdx.x;
    if (b < 1152) {
        int ub = b / 9, kc = b % 9;
        int r = tid >> 3, c0 = (tid & 7) * 16;
        int g = r & 3, ul = r >> 2;
        int j = g*1024 + ub*8 + ul;
        const float* src = (kc == 0) ? (W_ih1 + j*384 + 256)
                                     : (W_hh1 + j*1024 + (kc*128 - 128));
        for (int q = 0; q < 16; q += 4) {
            float4 v = *(const float4*)&src[c0+q];
            s[r][c0+q+0] = v.x; s[r][c0+q+1] = v.y;
            s[r][c0+q+2] = v.z; s[r][c0+q+3] = v.w;
        }
        __syncthreads();
        int rr = tid & 31, klg = tid >> 5;
        for (int kl = klg*16; kl < klg*16 + 16; kl++)
            g_Wt1[(kc*128 + kl)*G1 + ub*32 + rr] = s[rr][kl];
    } else {
        int bb = b - 1152;
        int ub = bb / 9, kc = bb % 9;
        int r = tid >> 4, c0 = (tid & 15) * 8;
        int g = r & 3, ul = r >> 2;
        int j = g*128 + ub*4 + ul;
        const float* src = (kc < 8) ? (W_ih2 + j*1024 + kc*128) : (W_hh2 + j*128);
        for (int q = 0; q < 8; q += 4) {
            float4 v = *(const float4*)&src[c0+q];
            s[r][c0+q+0] = v.x; s[r][c0+q+1] = v.y;
            s[r][c0+q+2] = v.z; s[r][c0+q+3] = v.w;
        }
        __syncthreads();
        int rr = tid & 15, klg = tid >> 4;
        for (int kl = klg*8; kl < klg*8 + 8; kl++)
            g_Wt2[(kc*128 + kl)*512 + ub*16 + rr] = s[rr][kl];
    }
}

// ---------------- big GEMM (A 256-wide row-major) ----------------
template<int LDB, int MODE>
__global__ __launch_bounds__(256) void kGemmBig(const float* __restrict__ A,
                                                const float* __restrict__ B,
                                                const float* __restrict__ bias1,
                                                const float* __restrict__ bias2,
                                                float* __restrict__ C, int Nc)
{
    __shared__ float As[16][132];
    __shared__ float Bs[16][68];
    int tid = threadIdx.x;
    int m_base = blockIdx.y * 128;
    int n_base = blockIdx.x * 64;
    int tm = tid & 15, tn = tid >> 4;
    int m0 = tm*8, n0 = tn*4;
    float acc[8][4];
#pragma unroll
    for (int i=0;i<8;i++)
#pragma unroll
        for (int j=0;j<4;j++) acc[i][j]=0.f;
    int a_row = tid >> 1, a_kq = (tid & 1)*8;
    int b_row = tid >> 2, b_kq = (tid & 3)*4;
    for (int kc = 0; kc < 256; kc += 16) {
        float4 a0 = *(const float4*)&A[(m_base + a_row)*256 + kc + a_kq];
        float4 a1 = *(const float4*)&A[(m_base + a_row)*256 + kc + a_kq + 4];
        float4 b0 = *(const float4*)&B[(n_base + b_row)*LDB + kc + b_kq];
        __syncthreads();
        As[a_kq+0][a_row]=a0.x; As[a_kq+1][a_row]=a0.y; As[a_kq+2][a_row]=a0.z; As[a_kq+3][a_row]=a0.w;
        As[a_kq+4][a_row]=a1.x; As[a_kq+5][a_row]=a1.y; As[a_kq+6][a_row]=a1.z; As[a_kq+7][a_row]=a1.w;
        Bs[b_kq+0][b_row]=b0.x; Bs[b_kq+1][b_row]=b0.y; Bs[b_kq+2][b_row]=b0.z; Bs[b_kq+3][b_row]=b0.w;
        __syncthreads();
#pragma unroll
        for (int kk = 0; kk < 16; kk++) {
            float4 av0 = *(const float4*)&As[kk][m0];
            float4 av1 = *(const float4*)&As[kk][m0+4];
            float4 bv  = *(const float4*)&Bs[kk][n0];
            float a8[8] = {av0.x,av0.y,av0.z,av0.w,av1.x,av1.y,av1.z,av1.w};
            float b4[4] = {bv.x,bv.y,bv.z,bv.w};
#pragma unroll
            for (int i=0;i<8;i++)
#pragma unroll
                for (int j=0;j<4;j++) acc[i][j] = fmaf(a8[i], b4[j], acc[i][j]);
        }
    }
    float bb[4];
#pragma unroll
    for (int j=0;j<4;j++) {
        int gj = n_base + n0 + j;
        bb[j] = bias1[gj] + (MODE==0 ? bias2[gj] : 0.f);
    }
#pragma unroll
    for (int i=0;i<8;i++) {
        int r = m_base + m0 + i;
        float4 v = make_float4(acc[i][0]+bb[0], acc[i][1]+bb[1], acc[i][2]+bb[2], acc[i][3]+bb[3]);
        if (MODE == 0) *(float4*)&C[r*Nc + n_base + n0] = v;
        else { int n = r & 31, t = r >> 5; *(float4*)&C[(n*LD + t)*Nc + n_base + n0] = v; }
    }
}

// ---------------- transpose Xg -> [t][j'][n] ----------------
__global__ __launch_bounds__(256) void kXgT()
{
    __shared__ float s[128][33];
    int t = blockIdx.x >> 5, jc = blockIdx.x & 31;
    int tid = threadIdx.x;
    for (int rep = 0; rep < 16; rep++) {
        int idx = rep*256 + tid;
        int n = idx >> 7, g = (idx >> 5) & 3, ul = idx & 31;
        s[ul*4+g][n] = g_Xg[(t*32+n)*G1 + g*1024 + jc*32 + ul];
    }
    __syncthreads();
    for (int rep = 0; rep < 16; rep++) {
        int idx = rep*256 + tid;
        int rr = idx >> 5, n = idx & 31;
        g_Xg2[((size_t)t*G1 + jc*128 + rr)*32 + n] = s[rr][n];
    }
}

// ---------------- persistent decoder ----------------
__global__ __launch_bounds__(256, 1) void kPersist(
    const float* __restrict__ key, const float* __restrict__ values,
    const int* __restrict__ elens,
    const float* __restrict__ b_ih2, const float* __restrict__ b_hh2)
{
    extern __shared__ float smem[];               // 147456 B
    __shared__ __align__(16) float sh2[128];
    __shared__ float es[512];
    __shared__ float red[256];
    __shared__ float cs[2][128];

    int bid = blockIdx.x, tid = threadIdx.x;

    for (int t = 0; t < LD; t++) {
        // ===== P1: LSTM1 GEMM (32 j' full-K) + cell fused =====
        {
            float4* d4 = (float4*)smem;
            const float4* s4 = (const float4*)g_A;
            for (int i = tid; i < 9216; i += 256) d4[i] = s4[i];
            __syncthreads();
            int ks = tid >> 5, w = tid & 31, nt = w >> 3, jt = w & 7;
            const float* wp = g_Wt1 + (ks*144)*G1 + bid*32 + jt*4;
            const float* ap = smem + (ks*144)*32 + nt*8;
            ull acc[4][4];
#pragma unroll
            for (int i=0;i<4;i++)
#pragma unroll
                for (int j=0;j<4;j++) acc[i][j] = 0ull;
#pragma unroll 4
            for (int k = 0; k < 144; k++) {
                float4 wv = __ldg((const float4*)wp); wp += G1;
                const ull* a8 = (const ull*)ap; ap += 32;
                ull a0=a8[0], a1=a8[1], a2=a8[2], a3=a8[3];
                ull w0=pack2(wv.x), w1=pack2(wv.y), w2=pack2(wv.z), w3=pack2(wv.w);
                fma2(acc[0][0],w0,a0); fma2(acc[0][1],w0,a1); fma2(acc[0][2],w0,a2); fma2(acc[0][3],w0,a3);
                fma2(acc[1][0],w1,a0); fma2(acc[1][1],w1,a1); fma2(acc[1][2],w1,a2); fma2(acc[1][3],w1,a3);
                fma2(acc[2][0],w2,a0); fma2(acc[2][1],w2,a1); fma2(acc[2][2],w2,a2); fma2(acc[2][3],w2,a3);
                fma2(acc[3][0],w3,a0); fma2(acc[3][1],w3,a1); fma2(acc[3][2],w3,a2); fma2(acc[3][3],w3,a3);
            }
            __syncthreads();
#pragma unroll
            for (int jj=0;jj<4;jj++)
#pragma unroll
                for (int p=0;p<4;p++)
                    *(ull*)&smem[(ks*32 + jt*4+jj)*32 + nt*8 + p*2] = acc[jj][p];
            __syncthreads();
            int u_loc = tid >> 5, n = tid & 31;
            int u_glob = bid*8 + u_loc;
            const float* xg = g_Xg2 + ((size_t)t*G1 + u_glob*4)*32 + n;
            float G[4];
#pragma unroll
            for (int g = 0; g < 4; g++) {
                float s = xg[g*32];
#pragma unroll
                for (int q = 0; q < 8; q++) s += smem[(q*32 + u_loc*4 + g)*32 + n];
                G[g] = s;
            }
            float i_ = sigm(G[0]), f_ = sigm(G[1]), gg = tanhf(G[2]), o_ = sigm(G[3]);
            float c = f_*g_c1[u_glob*32 + n] + i_*gg;
            g_c1[u_glob*32 + n] = c;
            g_A[(128 + u_glob)*32 + n] = o_*tanhf(c);
        }
        gbar();

        // ===== P2: LSTM2 GEMM partials (32 u-groups x 4 k-splits) =====
        {
            int ug = bid >> 2, ks2 = bid & 3;
            float4* d4 = (float4*)smem;
            for (int i4 = tid; i4 < 2304; i4 += 256) {          // 288*32/4
                int r = i4 >> 3;
                int ksrc = ks2*288 + r;
                const float4* src = (ksrc < 1024) ? (const float4*)&g_A[(128+ksrc)*32]
                                                  : (const float4*)&g_h2t[(ksrc-1024)*32];
                d4[i4] = src[i4 & 7];
            }
            __syncthreads();
            int kss = tid >> 5, w = tid & 31, nt = w >> 2, jt = w & 3;
            const float* wp = g_Wt2 + (ks2*288 + kss*36)*512 + ug*16 + jt*4;
            const float* ap = smem + (kss*36)*32 + nt*4;
            ull acc[4][2];
#pragma unroll
            for (int i=0;i<4;i++){ acc[i][0]=0ull; acc[i][1]=0ull; }
#pragma unroll 4
            for (int k = 0; k < 36; k++) {
                float4 wv = __ldg((const float4*)wp); wp += 512;
                ull a0 = *(const ull*)ap, a1 = *(const ull*)(ap+2); ap += 32;
                ull w0=pack2(wv.x), w1=pack2(wv.y), w2=pack2(wv.z), w3=pack2(wv.w);
                fma2(acc[0][0],w0,a0); fma2(acc[0][1],w0,a1);
                fma2(acc[1][0],w1,a0); fma2(acc[1][1],w1,a1);
                fma2(acc[2][0],w2,a0); fma2(acc[2][1],w2,a1);
                fma2(acc[3][0],w3,a0); fma2(acc[3][1],w3,a1);
            }
            __syncthreads();
#pragma unroll
            for (int jj=0;jj<4;jj++)
#pragma unroll
                for (int p=0;p<2;p++)
                    *(ull*)&smem[(kss*16 + jt*4+jj)*32 + nt*4 + p*2] = acc[jj][p];
            __syncthreads();
            for (int o = tid; o < 512; o += 256) {
                int jl = o >> 5, n = o & 31;
                float s = 0.f;
#pragma unroll
                for (int q = 0; q < 8; q++) s += smem[(q*16 + jl)*32 + n];
                g_p2[(ks2*512 + ug*16 + jl)*32 + n] = s;
            }
        }
        gbar();

        // ===== P3: cell2 + attention (blocks 0..31) =====
        if (bid < NB) {
            int n = bid;
            if (tid < 128) {
                int u = tid;
                float G2[4];
#pragma unroll
                for (int g = 0; g < 4; g++) {
                    float s = b_ih2[g*128+u] + b_hh2[g*128+u];
#pragma unroll
                    for (int sp = 0; sp < 4; sp++) s += g_p2[(sp*512 + u*4+g)*32 + n];
                    G2[g] = s;
                }
                float i_ = sigm(G2[0]), f_ = sigm(G2[1]), gg = tanhf(G2[2]), o_ = sigm(G2[3]);
                float c = f_*g_c2[n*128 + u] + i_*gg;
                g_c2[n*128 + u] = c;
                float h = o_*tanhf(c);
                sh2[u] = h;
                g_h2t[u*32 + n] = h;
                g_h2ctx[((size_t)t*32 + n)*256 + u] = h;
            }
            __syncthreads();
            int warp = tid >> 5, lane = tid & 31;
            int len = elens[n];
            float4 hv = ((const float4*)sh2)[lane];
            for (int te = warp; te < TE; te += 8) {
                const float4* kp = (const float4*)&key[((size_t)n*TE + te)*KSZ];
                float4 kv = kp[lane];
                float p = kv.x*hv.x + kv.y*hv.y + kv.z*hv.z + kv.w*hv.w;
                p += __shfl_xor_sync(0xffffffffu, p, 16);
                p += __shfl_xor_sync(0xffffffffu, p, 8);
                p += __shfl_xor_sync(0xffffffffu, p, 4);
                p += __shfl_xor_sync(0xffffffffu, p, 2);
                p += __shfl_xor_sync(0xffffffffu, p, 1);
                if (lane == 0) es[te] = (te >= len) ? -1.0e9f : p;
            }
            __syncthreads();
            float m = fmaxf(es[tid], es[tid + 256]);
            red[tid] = m;
            __syncthreads();
            for (int st = 128; st > 0; st >>= 1) {
                if (tid < st) red[tid] = fmaxf(red[tid], red[tid + st]);
                __syncthreads();
            }
            float mx = red[0];
            __syncthreads();
            float p0 = expf(es[tid] - mx);
            float p1 = expf(es[tid + 256] - mx);
            es[tid] = p0; es[tid + 256] = p1;
            red[tid] = p0 + p1;
            __syncthreads();
            for (int st = 128; st > 0; st >>= 1) {
                if (tid < st) red[tid] += red[tid + st];
                __syncthreads();
            }
            float inv = 1.0f / red[0];
            int v = tid & 127, half = tid >> 7;
            float acc = 0.f;
            int tb = half * 256;
#pragma unroll 4
            for (int te = tb; te < tb + 256; te++)
                acc += es[te] * values[((size_t)n*TE + te)*128 + v];
            cs[half][v] = acc;
            __syncthreads();
            if (tid < 128) {
                float ctx = (cs[0][tid] + cs[1][tid]) * inv;
                g_A[tid*32 + n] = ctx;
                g_h2ctx[((size_t)t*32 + n)*256 + 128 + tid] = ctx;
            }
        }
        if (t < LD-1) gbar();
    }
}

// ---------------- launch ----------------
extern "C" void kernel_launch(void* const* d_in, const int* in_sizes, int n_in,
                              void* d_out, int out_size)
{
    const float* key    = (const float*)d_in[0];
    const float* values = (const float*)d_in[1];
    const int*   elens  = (const int*)  d_in[2];
    const int*   text   = (const int*)  d_in[3];
    const float* emb    = (const float*)d_in[4];
    const float* W_ih1  = (const float*)d_in[5];
    const float* W_hh1  = (const float*)d_in[6];
    const float* b_ih1  = (const float*)d_in[7];
    const float* b_hh1  = (const float*)d_in[8];
    const float* W_ih2  = (const float*)d_in[9];
    const float* W_hh2  = (const float*)d_in[10];
    const float* b_ih2  = (const float*)d_in[11];
    const float* b_hh2  = (const float*)d_in[12];
    const float* W_out  = (const float*)d_in[13];
    const float* b_out  = (const float*)d_in[14];
    float* out = (float*)d_out;

    cudaFuncSetAttribute(kPersist, cudaFuncAttributeMaxDynamicSharedMemorySize, 147456);

    kInit<<<LD*NB + 304, 256>>>(text, emb, values);
    kPack<<<1440, 256>>>(W_ih1, W_hh1, W_ih2, W_hh2);

    float* gXg; cudaGetSymbolAddress((void**)&gXg, g_Xg);
    float* gX;  cudaGetSymbolAddress((void**)&gX, g_X);
    kGemmBig<384,0><<<dim3(G1/64, (LD*NB)/128), 256>>>(gX, W_ih1, b_ih1, b_hh1, gXg, G1);
    kXgT<<<4096, 256>>>();

    kPersist<<<NBLK, 256, 147456>>>(key, values, elens, b_ih2, b_hh2);

    float* gHC; cudaGetSymbolAddress((void**)&gHC, g_h2ctx);
    kGemmBig<256,1><<<dim3(VV/64, (LD*NB)/128), 256>>>(gHC, W_out, b_out, (const float*)0, out, VV);
}

// round 8
// speedup vs baseline: 1.3501x; 1.1144x over previous
#include <cuda_runtime.h>
#include <math.h>

#define NB 32
#define TE 512
#define LD 128
#define VV 8000
#define HH 1024
#define KSZ 128
#define G1 4096
#define KT 1152
#define NBLK 128
typedef unsigned long long ull;

__device__ __align__(16) float g_X[(LD*NB)*256];
__device__ __align__(16) float g_Xg[(LD*NB)*G1];
__device__ __align__(16) float g_Xg2[(size_t)LD*G1*NB];
__device__ __align__(16) float g_Wt1[KT*G1];        // [k][j'], j'=u*4+g
__device__ __align__(16) float g_Wt2[KT*512];       // [k][j'], j'=u*4+g
__device__ __align__(16) float g_A[KT*NB];          // [k][n]: k<128 ctx, k>=128 h1
__device__ __align__(16) float g_h2t[KSZ*NB];       // [k][n]
__device__ __align__(16) float g_c1[HH*NB];         // [u][n]
__device__ __align__(16) float g_c2[NB*KSZ];        // [n][u]
__device__ __align__(16) float g_hhp[3*G1*NB];      // [ks][j'][n] hh1 partials for next step
__device__ __align__(16) float g_g2T[NB*512];       // [n][j'] lstm2 gates
__device__ __align__(16) float g_h2ctx[(LD*NB)*256];
__device__ unsigned g_arrive = 0, g_gen = 0;
__device__ unsigned g_arr2 = 0, g_gen2 = 0;

__device__ __forceinline__ float sigm(float x){ return 1.0f/(1.0f + expf(-x)); }
__device__ __forceinline__ unsigned ldv(const unsigned* p){
    unsigned v; asm volatile("ld.volatile.global.u32 %0, [%1];" : "=r"(v) : "l"(p)); return v; }
__device__ __forceinline__ void stv(unsigned* p, unsigned v){
    asm volatile("st.volatile.global.u32 [%0], %1;" :: "l"(p), "r"(v)); }

__device__ __forceinline__ void gbarN(unsigned* arr, unsigned* gen, unsigned cnt)
{
    __syncthreads();
    if (threadIdx.x == 0) {
        __threadfence();
        unsigned g = ldv(gen);
        if (atomicAdd(arr, 1u) == cnt - 1u) {
            stv(arr, 0u);
            __threadfence();
            stv(gen, g + 1u);
        } else {
            while (ldv(gen) == g) __nanosleep(32);
        }
        __threadfence();
    }
    __syncthreads();
}

__device__ __forceinline__ void fma2(ull& d, ull a, ull b){
    asm("fma.rn.f32x2 %0, %1, %2, %0;" : "+l"(d) : "l"(a), "l"(b));
}
__device__ __forceinline__ ull pack2(float x){
    ull d; unsigned u = __float_as_uint(x);
    asm("mov.b64 %0, {%1, %1};" : "=l"(d) : "r"(u));
    return d;
}
__device__ __forceinline__ float lo2(ull v){ return __uint_as_float((unsigned)v); }
__device__ __forceinline__ float hi2(ull v){ return __uint_as_float((unsigned)(v >> 32)); }

// ---------------- init ----------------
__global__ __launch_bounds__(256) void kInit(const int* __restrict__ text,
                                             const float* __restrict__ emb,
                                             const float* __restrict__ values)
{
    int b = blockIdx.x, tid = threadIdx.x;
    if (b < LD*NB) {
        int t = b >> 5, n = b & 31;
        int idx = (t == 0) ? 1 : text[n*LD + (t-1)];
        g_X[b*256 + tid] = emb[idx*256 + tid];
    } else {
        int i = (b - LD*NB)*256 + tid;
        if      (i < 32768) g_c1[i] = 0.f;
        else if (i < 65536) g_A[4096 + (i - 32768)] = 0.f;
        else if (i < 69632) g_c2[i - 65536] = 0.f;
        else if (i < 73728) g_h2t[i - 69632] = 0.f;
        else if (i < 77824) { int u = i - 73728; int k = u >> 5, n = u & 31;
                              g_A[k*32 + n] = values[n*(TE*128) + k]; }
        else                g_hhp[i - 77824] = 0.f;
    }
}

// ---------------- weight repack to k-major ----------------
__global__ __launch_bounds__(256) void kPack(const float* __restrict__ W_ih1,
                                             const float* __restrict__ W_hh1,
                                             const float* __restrict__ W_ih2,
                                             const float* __restrict__ W_hh2)
{
    __shared__ float s[32][129];
    int b = blockIdx.x, tid = threadIdx.x;
    if (b < 1152) {
        int ub = b / 9, kc = b % 9;
        int r = tid >> 3, c0 = (tid & 7) * 16;
        int g = r & 3, ul = r >> 2;
        int j = g*1024 + ub*8 + ul;
        const float* src = (kc == 0) ? (W_ih1 + j*384 + 256)
                                     : (W_hh1 + j*1024 + (kc*128 - 128));
        for (int q = 0; q < 16; q += 4) {
            float4 v = *(const float4*)&src[c0+q];
            s[r][c0+q+0] = v.x; s[r][c0+q+1] = v.y;
            s[r][c0+q+2] = v.z; s[r][c0+q+3] = v.w;
        }
        __syncthreads();
        int rr = tid & 31, klg = tid >> 5;
        for (int kl = klg*16; kl < klg*16 + 16; kl++)
            g_Wt1[(kc*128 + kl)*G1 + ub*32 + rr] = s[rr][kl];
    } else {
        int bb = b - 1152;
        int ub = bb / 9, kc = bb % 9;
        int r = tid >> 4, c0 = (tid & 15) * 8;
        int g = r & 3, ul = r >> 2;
        int j = g*128 + ub*4 + ul;
        const float* src = (kc < 8) ? (W_ih2 + j*1024 + kc*128) : (W_hh2 + j*128);
        for (int q = 0; q < 8; q += 4) {
            float4 v = *(const float4*)&src[c0+q];
            s[r][c0+q+0] = v.x; s[r][c0+q+1] = v.y;
            s[r][c0+q+2] = v.z; s[r][c0+q+3] = v.w;
        }
        __syncthreads();
        int rr = tid & 15, klg = tid >> 4;
        for (int kl = klg*8; kl < klg*8 + 8; kl++)
            g_Wt2[(kc*128 + kl)*512 + ub*16 + rr] = s[rr][kl];
    }
}

// ---------------- big GEMM, f32x2 inner ----------------
template<int LDB, int MODE>
__global__ __launch_bounds__(256) void kGemmBig(const float* __restrict__ A,
                                                const float* __restrict__ B,
                                                const float* __restrict__ bias1,
                                                const float* __restrict__ bias2,
                                                float* __restrict__ C, int Nc)
{
    __shared__ float As[16][132];
    __shared__ float Bs[16][68];
    int tid = threadIdx.x;
    int m_base = blockIdx.y * 128;
    int n_base = blockIdx.x * 64;
    int tm = tid & 15, tn = tid >> 4;
    int m0 = tm*8, n0 = tn*4;
    ull acc[8][2];
#pragma unroll
    for (int i=0;i<8;i++){ acc[i][0]=0ull; acc[i][1]=0ull; }
    int a_row = tid >> 1, a_kq = (tid & 1)*8;
    int b_row = tid >> 2, b_kq = (tid & 3)*4;
    for (int kc = 0; kc < 256; kc += 16) {
        float4 a0 = *(const float4*)&A[(m_base + a_row)*256 + kc + a_kq];
        float4 a1 = *(const float4*)&A[(m_base + a_row)*256 + kc + a_kq + 4];
        float4 b0 = *(const float4*)&B[(size_t)(n_base + b_row)*LDB + kc + b_kq];
        __syncthreads();
        As[a_kq+0][a_row]=a0.x; As[a_kq+1][a_row]=a0.y; As[a_kq+2][a_row]=a0.z; As[a_kq+3][a_row]=a0.w;
        As[a_kq+4][a_row]=a1.x; As[a_kq+5][a_row]=a1.y; As[a_kq+6][a_row]=a1.z; As[a_kq+7][a_row]=a1.w;
        Bs[b_kq+0][b_row]=b0.x; Bs[b_kq+1][b_row]=b0.y; Bs[b_kq+2][b_row]=b0.z; Bs[b_kq+3][b_row]=b0.w;
        __syncthreads();
#pragma unroll
        for (int kk = 0; kk < 16; kk++) {
            float4 av0 = *(const float4*)&As[kk][m0];
            float4 av1 = *(const float4*)&As[kk][m0+4];
            ull bv0 = *(const ull*)&Bs[kk][n0];
            ull bv1 = *(const ull*)&Bs[kk][n0+2];
            float a8[8] = {av0.x,av0.y,av0.z,av0.w,av1.x,av1.y,av1.z,av1.w};
#pragma unroll
            for (int i=0;i<8;i++) {
                ull ai = pack2(a8[i]);
                fma2(acc[i][0], ai, bv0);
                fma2(acc[i][1], ai, bv1);
            }
        }
    }
    float bb[4];
#pragma unroll
    for (int j=0;j<4;j++) {
        int gj = n_base + n0 + j;
        bb[j] = bias1[gj] + (MODE==0 ? bias2[gj] : 0.f);
    }
#pragma unroll
    for (int i=0;i<8;i++) {
        int r = m_base + m0 + i;
        float4 v = make_float4(lo2(acc[i][0])+bb[0], hi2(acc[i][0])+bb[1],
                               lo2(acc[i][1])+bb[2], hi2(acc[i][1])+bb[3]);
        if (MODE == 0) *(float4*)&C[(size_t)r*Nc + n_base + n0] = v;
        else { int n = r & 31, t = r >> 5; *(float4*)&C[((size_t)n*LD + t)*Nc + n_base + n0] = v; }
    }
}

// ---------------- transpose Xg -> [t][j'][n] ----------------
__global__ __launch_bounds__(256) void kXgT()
{
    __shared__ float s[128][33];
    int t = blockIdx.x >> 5, jc = blockIdx.x & 31;
    int tid = threadIdx.x;
    for (int rep = 0; rep < 16; rep++) {
        int idx = rep*256 + tid;
        int n = idx >> 7, g = (idx >> 5) & 3, ul = idx & 31;
        s[ul*4+g][n] = g_Xg[(t*32+n)*G1 + g*1024 + jc*32 + ul];
    }
    __syncthreads();
    for (int rep = 0; rep < 16; rep++) {
        int idx = rep*256 + tid;
        int rr = idx >> 5, n = idx & 31;
        g_Xg2[((size_t)t*G1 + jc*128 + rr)*32 + n] = s[rr][n];
    }
}

// ---------------- persistent decoder ----------------
__global__ __launch_bounds__(256, 1) void kPersist(
    const float* __restrict__ key, const float* __restrict__ values,
    const int* __restrict__ elens,
    const float* __restrict__ b_ih2, const float* __restrict__ b_hh2)
{
    extern __shared__ float smem[];               // 147456 B
    __shared__ __align__(16) float sh2[128];
    __shared__ float es[512];
    __shared__ float red[256];
    __shared__ float cs[2][128];

    int bid = blockIdx.x, tid = threadIdx.x;
    int wid = tid >> 5, w = tid & 31;

    for (int t = 0; t < LD; t++) {
        // ===== P1': ctx GEMM (K=128) + hh/Xg reduce + cell1 =====
        {
            float4* d4 = (float4*)smem;
            for (int i = tid; i < 1024; i += 256) d4[i] = ((const float4*)g_A)[i];
            __syncthreads();
            int nt = w >> 3, jt = w & 7;
            const float* wp = g_Wt1 + (wid*16)*G1 + bid*32 + jt*4;
            const float* ap = smem + (wid*16)*32 + nt*8;
            ull acc[4][4];
#pragma unroll
            for (int i=0;i<4;i++)
#pragma unroll
                for (int j=0;j<4;j++) acc[i][j] = 0ull;
#pragma unroll
            for (int k = 0; k < 16; k++) {
                float4 wv = __ldg((const float4*)wp); wp += G1;
                const ull* a8 = (const ull*)ap; ap += 32;
                ull a0=a8[0], a1=a8[1], a2=a8[2], a3=a8[3];
                ull w0=pack2(wv.x), w1=pack2(wv.y), w2=pack2(wv.z), w3=pack2(wv.w);
                fma2(acc[0][0],w0,a0); fma2(acc[0][1],w0,a1); fma2(acc[0][2],w0,a2); fma2(acc[0][3],w0,a3);
                fma2(acc[1][0],w1,a0); fma2(acc[1][1],w1,a1); fma2(acc[1][2],w1,a2); fma2(acc[1][3],w1,a3);
                fma2(acc[2][0],w2,a0); fma2(acc[2][1],w2,a1); fma2(acc[2][2],w2,a2); fma2(acc[2][3],w2,a3);
                fma2(acc[3][0],w3,a0); fma2(acc[3][1],w3,a1); fma2(acc[3][2],w3,a2); fma2(acc[3][3],w3,a3);
            }
            __syncthreads();
#pragma unroll
            for (int jj=0;jj<4;jj++)
#pragma unroll
                for (int p=0;p<4;p++)
                    *(ull*)&smem[(wid*32 + jt*4+jj)*32 + nt*8 + p*2] = acc[jj][p];
            __syncthreads();
            int u_loc = tid >> 5, n = tid & 31;
            int u_glob = bid*8 + u_loc;
            float G[4];
#pragma unroll
            for (int g = 0; g < 4; g++) {
                int jp = u_glob*4 + g;
                float s = g_Xg2[((size_t)t*G1 + jp)*32 + n];
#pragma unroll
                for (int sp = 0; sp < 3; sp++) s += g_hhp[((size_t)sp*G1 + jp)*32 + n];
#pragma unroll
                for (int q = 0; q < 8; q++) s += smem[(q*32 + u_loc*4 + g)*32 + n];
                G[g] = s;
            }
            float i_ = sigm(G[0]), f_ = sigm(G[1]), gg = tanhf(G[2]), o_ = sigm(G[3]);
            float c = f_*g_c1[u_glob*32 + n] + i_*gg;
            g_c1[u_glob*32 + n] = c;
            g_A[(128 + u_glob)*32 + n] = o_*tanhf(c);
        }
        gbarN(&g_arrive, &g_gen, NBLK);

        if (bid < NB) {
            // ===== P2': LSTM2 gates, j-slice 16 per block, full K=1152 =====
            {
                float4* d4 = (float4*)smem;
                for (int i4 = tid; i4 < 9216; i4 += 256) {
                    int r = i4 >> 3;
                    const float4* src = (r < 1024) ? (const float4*)&g_A[(128+r)*32]
                                                   : (const float4*)&g_h2t[(r-1024)*32];
                    d4[i4] = src[i4 & 7];
                }
                __syncthreads();
                int nt = w >> 2, jt = w & 3;
                const float* wp = g_Wt2 + (wid*144)*512 + bid*16 + jt*4;
                const float* ap = smem + (wid*144)*32 + nt*4;
                ull acc[4][2];
#pragma unroll
                for (int i=0;i<4;i++){ acc[i][0]=0ull; acc[i][1]=0ull; }
#pragma unroll 4
                for (int k = 0; k < 144; k++) {
                    float4 wv = __ldg((const float4*)wp); wp += 512;
                    ull a0 = *(const ull*)ap, a1 = *(const ull*)(ap+2); ap += 32;
                    ull w0=pack2(wv.x), w1=pack2(wv.y), w2=pack2(wv.z), w3=pack2(wv.w);
                    fma2(acc[0][0],w0,a0); fma2(acc[0][1],w0,a1);
                    fma2(acc[1][0],w1,a0); fma2(acc[1][1],w1,a1);
                    fma2(acc[2][0],w2,a0); fma2(acc[2][1],w2,a1);
                    fma2(acc[3][0],w3,a0); fma2(acc[3][1],w3,a1);
                }
                __syncthreads();
#pragma unroll
                for (int jj=0;jj<4;jj++)
#pragma unroll
                    for (int p=0;p<2;p++)
                        *(ull*)&smem[(wid*16 + jt*4+jj)*32 + nt*4 + p*2] = acc[jj][p];
                __syncthreads();
                for (int o = tid; o < 512; o += 256) {
                    int jl = o >> 5, n = o & 31;
                    float s = 0.f;
#pragma unroll
                    for (int q = 0; q < 8; q++) s += smem[(q*16 + jl)*32 + n];
                    g_g2T[n*512 + bid*16 + jl] = s;
                }
            }
            gbarN(&g_arr2, &g_gen2, 32);

            // ===== P3: cell2 + attention, n = bid =====
            int n = bid;
            if (tid < 128) {
                int u = tid;
                float4 gv = *(const float4*)&g_g2T[n*512 + u*4];
                float i_ = sigm(gv.x + b_ih2[u]       + b_hh2[u]);
                float f_ = sigm(gv.y + b_ih2[128+u]   + b_hh2[128+u]);
                float gg = tanhf(gv.z + b_ih2[256+u]  + b_hh2[256+u]);
                float o_ = sigm(gv.w + b_ih2[384+u]   + b_hh2[384+u]);
                float c = f_*g_c2[n*128 + u] + i_*gg;
                g_c2[n*128 + u] = c;
                float h = o_*tanhf(c);
                sh2[u] = h;
                g_h2t[u*32 + n] = h;
                g_h2ctx[((size_t)t*32 + n)*256 + u] = h;
            }
            __syncthreads();
            int warp = wid, lane = w;
            int len = elens[n];
            float4 hv = ((const float4*)sh2)[lane];
            for (int tb = warp*4; tb < TE; tb += 32) {
                float p[4];
#pragma unroll
                for (int i=0;i<4;i++) {
                    float4 kv = ((const float4*)&key[((size_t)n*TE + tb + i)*KSZ])[lane];
                    p[i] = kv.x*hv.x + kv.y*hv.y + kv.z*hv.z + kv.w*hv.w;
                }
#pragma unroll
                for (int sh = 16; sh > 0; sh >>= 1) {
#pragma unroll
                    for (int i=0;i<4;i++) p[i] += __shfl_xor_sync(0xffffffffu, p[i], sh);
                }
                if (lane < 4) es[tb + lane] = (tb + lane >= len) ? -1.0e9f : p[lane];
            }
            __syncthreads();
            float m = fmaxf(es[tid], es[tid + 256]);
            red[tid] = m;
            __syncthreads();
            for (int st = 128; st > 0; st >>= 1) {
                if (tid < st) red[tid] = fmaxf(red[tid], red[tid + st]);
                __syncthreads();
            }
            float mx = red[0];
            __syncthreads();
            float p0 = expf(es[tid] - mx);
            float p1 = expf(es[tid + 256] - mx);
            es[tid] = p0; es[tid + 256] = p1;
            red[tid] = p0 + p1;
            __syncthreads();
            for (int st = 128; st > 0; st >>= 1) {
                if (tid < st) red[tid] += red[tid + st];
                __syncthreads();
            }
            float inv = 1.0f / red[0];
            int v = tid & 127, half = tid >> 7;
            float acc = 0.f;
            int tbase = half * 256;
#pragma unroll 4
            for (int te = tbase; te < tbase + 256; te++)
                acc += es[te] * values[((size_t)n*TE + te)*128 + v];
            cs[half][v] = acc;
            __syncthreads();
            if (tid < 128) {
                float ctx = (cs[0][tid] + cs[1][tid]) * inv;
                g_A[tid*32 + n] = ctx;
                g_h2ctx[((size_t)t*32 + n)*256 + 128 + tid] = ctx;
            }
        } else if (t < LD-1) {
            // ===== hh-GEMM for step t+1: blocks 32..127 = 32 jc x 3 ks =====
            int idx = bid - 32;
            int jc = idx / 3, ks3 = idx - jc*3;
            int kstart = (ks3==0) ? 0 : ((ks3==1) ? 344 : 684);
            int sz = (ks3==0) ? 344 : 340;
            {
                float4* d4 = (float4*)smem;
                const float4* src = (const float4*)&g_A[(128 + kstart)*32];
                int n4 = sz * 8;
                for (int i4 = tid; i4 < n4; i4 += 256) d4[i4] = src[i4];
            }
            __syncthreads();
            int jg = wid & 3, ksub = wid >> 2;
            int h = sz >> 1;
            int nt = w >> 3, jt = w & 7;
            const float* wp = g_Wt1 + (size_t)(128 + kstart + ksub*h)*G1 + jc*128 + jg*32 + jt*4;
            const float* ap = smem + (ksub*h)*32 + nt*8;
            ull acc[4][4];
#pragma unroll
            for (int i=0;i<4;i++)
#pragma unroll
                for (int j=0;j<4;j++) acc[i][j] = 0ull;
#pragma unroll 4
            for (int k = 0; k < h; k++) {
                float4 wv = __ldg((const float4*)wp); wp += G1;
                const ull* a8 = (const ull*)ap; ap += 32;
                ull a0=a8[0], a1=a8[1], a2=a8[2], a3=a8[3];
                ull w0=pack2(wv.x), w1=pack2(wv.y), w2=pack2(wv.z), w3=pack2(wv.w);
                fma2(acc[0][0],w0,a0); fma2(acc[0][1],w0,a1); fma2(acc[0][2],w0,a2); fma2(acc[0][3],w0,a3);
                fma2(acc[1][0],w1,a0); fma2(acc[1][1],w1,a1); fma2(acc[1][2],w1,a2); fma2(acc[1][3],w1,a3);
                fma2(acc[2][0],w2,a0); fma2(acc[2][1],w2,a1); fma2(acc[2][2],w2,a2); fma2(acc[2][3],w2,a3);
                fma2(acc[3][0],w3,a0); fma2(acc[3][1],w3,a1); fma2(acc[3][2],w3,a2); fma2(acc[3][3],w3,a3);
            }
            __syncthreads();
#pragma unroll
            for (int jj=0;jj<4;jj++)
#pragma unroll
                for (int p=0;p<4;p++)
                    *(ull*)&smem[11264 + (ksub*128 + jg*32 + jt*4+jj)*32 + nt*8 + p*2] = acc[jj][p];
            __syncthreads();
            for (int o = tid; o < 4096; o += 256) {
                int jl = o >> 5, n = o & 31;
                float s = smem[11264 + jl*32 + n] + smem[11264 + 4096 + jl*32 + n];
                g_hhp[((size_t)ks3*G1 + jc*128 + jl)*32 + n] = s;
            }
        }
        gbarN(&g_arrive, &g_gen, NBLK);
    }
}

// ---------------- launch ----------------
extern "C" void kernel_launch(void* const* d_in, const int* in_sizes, int n_in,
                              void* d_out, int out_size)
{
    const float* key    = (const float*)d_in[0];
    const float* values = (const float*)d_in[1];
    const int*   elens  = (const int*)  d_in[2];
    const int*   text   = (const int*)  d_in[3];
    const float* emb    = (const float*)d_in[4];
    const float* W_ih1  = (const float*)d_in[5];
    const float* W_hh1  = (const float*)d_in[6];
    const float* b_ih1  = (const float*)d_in[7];
    const float* b_hh1  = (const float*)d_in[8];
    const float* W_ih2  = (const float*)d_in[9];
    const float* W_hh2  = (const float*)d_in[10];
    const float* b_ih2  = (const float*)d_in[11];
    const float* b_hh2  = (const float*)d_in[12];
    const float* W_out  = (const float*)d_in[13];
    const float* b_out  = (const float*)d_in[14];
    float* out = (float*)d_out;

    cudaFuncSetAttribute(kPersist, cudaFuncAttributeMaxDynamicSharedMemorySize, 147456);

    kInit<<<LD*NB + 1840, 256>>>(text, emb, values);
    kPack<<<1440, 256>>>(W_ih1, W_hh1, W_ih2, W_hh2);

    float* gXg; cudaGetSymbolAddress((void**)&gXg, g_Xg);
    float* gX;  cudaGetSymbolAddress((void**)&gX, g_X);
    kGemmBig<384,0><<<dim3(G1/64, (LD*NB)/128), 256>>>(gX, W_ih1, b_ih1, b_hh1, gXg, G1);
    kXgT<<<4096, 256>>>();

    kPersist<<<NBLK, 256, 147456>>>(key, values, elens, b_ih2, b_hh2);

    float* gHC; cudaGetSymbolAddress((void**)&gHC, g_h2ctx);
    kGemmBig<256,1><<<dim3(VV/64, (LD*NB)/128), 256>>>(gHC, W_out, b_out, (const float*)0, out, VV);
}

// round 9
// speedup vs baseline: 1.6456x; 1.2188x over previous
#include <cuda_runtime.h>
#include <cuda_bf16.h>
#include <math.h>

#define NB 32
#define TE 512
#define LD 128
#define VV 8000
#define HH 1024
#define KSZ 128
#define G1 4096
#define KT 1152
#define NBLK 128
typedef unsigned long long ull;

__device__ __align__(16) float g_X[(LD*NB)*256];
__device__ __align__(16) float g_Xg[(LD*NB)*G1];
__device__ __align__(16) float g_Xg2[(size_t)LD*G1*NB];
__device__ __align__(16) float g_Wt1[KT*G1];        // ctx part used ([k][j'])
__device__ __align__(16) float g_Wt2[KT*512];       // unused (kept)
__device__ __align__(16) float g_A[KT*NB];          // [k][n]: k<128 ctx (fp32)
__device__ __align__(16) float g_h2t[KSZ*NB];       // unused (kept)
__device__ __align__(16) float g_c1[HH*NB];         // [u][n]
__device__ __align__(16) float g_c2[NB*KSZ];        // [n][u]
__device__ __align__(16) float g_hhp[3*G1*NB];      // [ks][j'][n] hh1 partials
__device__ __align__(16) float g_g2T[NB*512];       // [n][j'] lstm2 gates
__device__ __align__(16) float g_h2ctx[(LD*NB)*256];
// mma fragment-packed weights (hi/lo bf16 split)
__device__ uint4 g_W1f_hi[524288], g_W1f_lo[524288];   // 256 mt x 64 kt x 32 lanes
__device__ uint4 g_W2f_hi[73728],  g_W2f_lo[73728];    // 32 mt x 72 kt x 32 lanes
// activation B-fragments: ktA 0..63 = h1, 64..71 = h2 ; [ktA][n8][lane][2 regs] u32
__device__ unsigned g_Af_hi[18432], g_Af_lo[18432];
__device__ unsigned g_arrive = 0, g_gen = 0;
__device__ unsigned g_arr2 = 0, g_gen2 = 0;

__device__ __forceinline__ float sigm(float x){ return 1.0f/(1.0f + expf(-x)); }
__device__ __forceinline__ unsigned ldv(const unsigned* p){
    unsigned v; asm volatile("ld.volatile.global.u32 %0, [%1];" : "=r"(v) : "l"(p)); return v; }
__device__ __forceinline__ void stv(unsigned* p, unsigned v){
    asm volatile("st.volatile.global.u32 [%0], %1;" :: "l"(p), "r"(v)); }

__device__ __forceinline__ void gbarN(unsigned* arr, unsigned* gen, unsigned cnt)
{
    __syncthreads();
    if (threadIdx.x == 0) {
        __threadfence();
        unsigned g = ldv(gen);
        if (atomicAdd(arr, 1u) == cnt - 1u) {
            stv(arr, 0u);
            __threadfence();
            stv(gen, g + 1u);
        } else {
            while (ldv(gen) == g) __nanosleep(32);
        }
        __threadfence();
    }
    __syncthreads();
}

__device__ __forceinline__ void fma2(ull& d, ull a, ull b){
    asm("fma.rn.f32x2 %0, %1, %2, %0;" : "+l"(d) : "l"(a), "l"(b));
}
__device__ __forceinline__ ull pack2(float x){
    ull d; unsigned u = __float_as_uint(x);
    asm("mov.b64 %0, {%1, %1};" : "=l"(d) : "r"(u));
    return d;
}
__device__ __forceinline__ float lo2(ull v){ return __uint_as_float((unsigned)v); }
__device__ __forceinline__ float hi2(ull v){ return __uint_as_float((unsigned)(v >> 32)); }

__device__ __forceinline__ void mma16816(float* d, uint4 a, unsigned b0, unsigned b1){
    asm("mma.sync.aligned.m16n8k16.row.col.f32.bf16.bf16.f32 "
        "{%0,%1,%2,%3}, {%4,%5,%6,%7}, {%8,%9}, {%0,%1,%2,%3};"
        : "+f"(d[0]), "+f"(d[1]), "+f"(d[2]), "+f"(d[3])
        : "r"(a.x), "r"(a.y), "r"(a.z), "r"(a.w), "r"(b0), "r"(b1));
}
__device__ __forceinline__ unsigned pbf(float e0, float e1, float* r0, float* r1){
    __nv_bfloat16 h0 = __float2bfloat16(e0), h1 = __float2bfloat16(e1);
    *r0 = e0 - __bfloat162float(h0);
    *r1 = e1 - __bfloat162float(h1);
    unsigned short x = __bfloat16_as_ushort(h0), y = __bfloat16_as_ushort(h1);
    return (unsigned)x | ((unsigned)y << 16);
}
// write one activation value into hi/lo B-fragment buffers
__device__ __forceinline__ void af_write(int ktA, int n, int kp, float v){
    __nv_bfloat16 bh = __float2bfloat16(v);
    __nv_bfloat16 bl = __float2bfloat16(v - __bfloat162float(bh));
    int n8 = n >> 3, np = n & 7;
    int lane = np*4 + ((kp & 7) >> 1);
    int reg = kp >> 3, half = kp & 1;
    size_t bi = ((((size_t)ktA*4 + n8)*32 + lane)*2 + reg)*2 + half;
    ((__nv_bfloat16*)g_Af_hi)[bi] = bh;
    ((__nv_bfloat16*)g_Af_lo)[bi] = bl;
}

// ---------------- init ----------------
__global__ __launch_bounds__(256) void kInit(const int* __restrict__ text,
                                             const float* __restrict__ emb,
                                             const float* __restrict__ values)
{
    int b = blockIdx.x, tid = threadIdx.x;
    if (b < LD*NB) {
        int t = b >> 5, n = b & 31;
        int idx = (t == 0) ? 1 : text[n*LD + (t-1)];
        g_X[b*256 + tid] = emb[idx*256 + tid];
    } else {
        int i = (b - LD*NB)*256 + tid;
        if      (i < 32768) g_c1[i] = 0.f;
        else if (i < 65536) g_A[4096 + (i - 32768)] = 0.f;
        else if (i < 69632) g_c2[i - 65536] = 0.f;
        else if (i < 73728) g_h2t[i - 69632] = 0.f;
        else if (i < 77824) { int u = i - 73728; int k = u >> 5, n = u & 31;
                              g_A[k*32 + n] = values[n*(TE*128) + k]; }
        else if (i < 471040) g_hhp[i - 77824] = 0.f;
        else { int z = i - 471040;
               if (z < 18432) g_Af_hi[z] = 0u;
               else if (z < 36864) g_Af_lo[z - 18432] = 0u; }
    }
}

// ---------------- weight repack (ctx part k-major, legacy) ----------------
__global__ __launch_bounds__(256) void kPack(const float* __restrict__ W_ih1,
                                             const float* __restrict__ W_hh1)
{
    __shared__ float s[32][129];
    int b = blockIdx.x, tid = threadIdx.x;
    int ub = b / 9, kc = b % 9;
    int r = tid >> 3, c0 = (tid & 7) * 16;
    int g = r & 3, ul = r >> 2;
    int j = g*1024 + ub*8 + ul;
    const float* src = (kc == 0) ? (W_ih1 + j*384 + 256)
                                 : (W_hh1 + j*1024 + (kc*128 - 128));
    for (int q = 0; q < 16; q += 4) {
        float4 v = *(const float4*)&src[c0+q];
        s[r][c0+q+0] = v.x; s[r][c0+q+1] = v.y;
        s[r][c0+q+2] = v.z; s[r][c0+q+3] = v.w;
    }
    __syncthreads();
    int rr = tid & 31, klg = tid >> 5;
    for (int kl = klg*16; kl < klg*16 + 16; kl++)
        g_Wt1[(kc*128 + kl)*G1 + ub*32 + rr] = s[rr][kl];
}

// ---------------- fragment pack: W_hh1 and W2 -> hi/lo bf16 fragments ----------------
__global__ __launch_bounds__(256) void kPackF(const float* __restrict__ W_hh1,
                                              const float* __restrict__ W_ih2,
                                              const float* __restrict__ W_hh2)
{
    int b = blockIdx.x, tid = threadIdx.x, wid = tid >> 5, l = tid & 31;
    if (b < 2048) {
        int tile = b*8 + wid;                     // 16384 tiles
        int mt = tile >> 6, kt = tile & 63;
        unsigned hi[4], lo[4];
#pragma unroll
        for (int p = 0; p < 4; p++) {
            int jp = mt*16 + (l>>2) + (p&1)*8;
            int u = jp >> 2, g = jp & 3;
            int k = kt*16 + (l&3)*2 + ((p>>1)&1)*8;
            const float* src = W_hh1 + (size_t)(g*1024+u)*1024 + k;
            float r0, r1;
            hi[p] = pbf(src[0], src[1], &r0, &r1);
            __nv_bfloat16 l0 = __float2bfloat16(r0), l1 = __float2bfloat16(r1);
            lo[p] = (unsigned)__bfloat16_as_ushort(l0) | ((unsigned)__bfloat16_as_ushort(l1) << 16);
        }
        g_W1f_hi[(size_t)tile*32 + l] = make_uint4(hi[0],hi[1],hi[2],hi[3]);
        g_W1f_lo[(size_t)tile*32 + l] = make_uint4(lo[0],lo[1],lo[2],lo[3]);
    } else {
        int tile = (b - 2048)*8 + wid;            // 2304 tiles
        if (tile >= 2304) return;
        int mt = tile / 72, kt = tile - mt*72;
        unsigned hi[4], lo[4];
#pragma unroll
        for (int p = 0; p < 4; p++) {
            int jp = mt*16 + (l>>2) + (p&1)*8;
            int u = jp >> 2, g = jp & 3;
            int k = kt*16 + (l&3)*2 + ((p>>1)&1)*8;
            const float* src = (k < 1024) ? (W_ih2 + (size_t)(g*128+u)*1024 + k)
                                          : (W_hh2 + (size_t)(g*128+u)*128 + (k - 1024));
            float r0, r1;
            hi[p] = pbf(src[0], src[1], &r0, &r1);
            __nv_bfloat16 l0 = __float2bfloat16(r0), l1 = __float2bfloat16(r1);
            lo[p] = (unsigned)__bfloat16_as_ushort(l0) | ((unsigned)__bfloat16_as_ushort(l1) << 16);
        }
        g_W2f_hi[(size_t)tile*32 + l] = make_uint4(hi[0],hi[1],hi[2],hi[3]);
        g_W2f_lo[(size_t)tile*32 + l] = make_uint4(lo[0],lo[1],lo[2],lo[3]);
    }
}

// ---------------- big GEMM, f32x2 inner ----------------
template<int LDB, int MODE>
__global__ __launch_bounds__(256) void kGemmBig(const float* __restrict__ A,
                                                const float* __restrict__ B,
                                                const float* __restrict__ bias1,
                                                const float* __restrict__ bias2,
                                                float* __restrict__ C, int Nc)
{
    __shared__ float As[16][132];
    __shared__ float Bs[16][68];
    int tid = threadIdx.x;
    int m_base = blockIdx.y * 128;
    int n_base = blockIdx.x * 64;
    int tm = tid & 15, tn = tid >> 4;
    int m0 = tm*8, n0 = tn*4;
    ull acc[8][2];
#pragma unroll
    for (int i=0;i<8;i++){ acc[i][0]=0ull; acc[i][1]=0ull; }
    int a_row = tid >> 1, a_kq = (tid & 1)*8;
    int b_row = tid >> 2, b_kq = (tid & 3)*4;
    for (int kc = 0; kc < 256; kc += 16) {
        float4 a0 = *(const float4*)&A[(m_base + a_row)*256 + kc + a_kq];
        float4 a1 = *(const float4*)&A[(m_base + a_row)*256 + kc + a_kq + 4];
        float4 b0 = *(const float4*)&B[(size_t)(n_base + b_row)*LDB + kc + b_kq];
        __syncthreads();
        As[a_kq+0][a_row]=a0.x; As[a_kq+1][a_row]=a0.y; As[a_kq+2][a_row]=a0.z; As[a_kq+3][a_row]=a0.w;
        As[a_kq+4][a_row]=a1.x; As[a_kq+5][a_row]=a1.y; As[a_kq+6][a_row]=a1.z; As[a_kq+7][a_row]=a1.w;
        Bs[b_kq+0][b_row]=b0.x; Bs[b_kq+1][b_row]=b0.y; Bs[b_kq+2][b_row]=b0.z; Bs[b_kq+3][b_row]=b0.w;
        __syncthreads();
#pragma unroll
        for (int kk = 0; kk < 16; kk++) {
            float4 av0 = *(const float4*)&As[kk][m0];
            float4 av1 = *(const float4*)&As[kk][m0+4];
            ull bv0 = *(const ull*)&Bs[kk][n0];
            ull bv1 = *(const ull*)&Bs[kk][n0+2];
            float a8[8] = {av0.x,av0.y,av0.z,av0.w,av1.x,av1.y,av1.z,av1.w};
#pragma unroll
            for (int i=0;i<8;i++) {
                ull ai = pack2(a8[i]);
                fma2(acc[i][0], ai, bv0);
                fma2(acc[i][1], ai, bv1);
            }
        }
    }
    float bb[4];
#pragma unroll
    for (int j=0;j<4;j++) {
        int gj = n_base + n0 + j;
        bb[j] = bias1[gj] + (MODE==0 ? bias2[gj] : 0.f);
    }
#pragma unroll
    for (int i=0;i<8;i++) {
        int r = m_base + m0 + i;
        float4 v = make_float4(lo2(acc[i][0])+bb[0], hi2(acc[i][0])+bb[1],
                               lo2(acc[i][1])+bb[2], hi2(acc[i][1])+bb[3]);
        if (MODE == 0) *(float4*)&C[(size_t)r*Nc + n_base + n0] = v;
        else { int n = r & 31, t = r >> 5; *(float4*)&C[((size_t)n*LD + t)*Nc + n_base + n0] = v; }
    }
}

// ---------------- transpose Xg -> [t][j'][n] ----------------
__global__ __launch_bounds__(256) void kXgT()
{
    __shared__ float s[128][33];
    int t = blockIdx.x >> 5, jc = blockIdx.x & 31;
    int tid = threadIdx.x;
    for (int rep = 0; rep < 16; rep++) {
        int idx = rep*256 + tid;
        int n = idx >> 7, g = (idx >> 5) & 3, ul = idx & 31;
        s[ul*4+g][n] = g_Xg[(t*32+n)*G1 + g*1024 + jc*32 + ul];
    }
    __syncthreads();
    for (int rep = 0; rep < 16; rep++) {
        int idx = rep*256 + tid;
        int rr = idx >> 5, n = idx & 31;
        g_Xg2[((size_t)t*G1 + jc*128 + rr)*32 + n] = s[rr][n];
    }
}

// ---------------- persistent decoder ----------------
__global__ __launch_bounds__(256, 1) void kPersist(
    const float* __restrict__ key, const float* __restrict__ values,
    const int* __restrict__ elens,
    const float* __restrict__ b_ih2, const float* __restrict__ b_hh2)
{
    extern __shared__ float smem[];               // 32 KB
    __shared__ __align__(16) float sh2[128];
    __shared__ float es[512];
    __shared__ float red[256];
    __shared__ float cs[2][128];

    int bid = blockIdx.x, tid = threadIdx.x;
    int wid = tid >> 5, w = tid & 31;

    for (int t = 0; t < LD; t++) {
        // ===== P1: ctx GEMM (fp32, K=128) + hh/Xg reduce + cell1 =====
        {
            float4* d4 = (float4*)smem;
            for (int i = tid; i < 1024; i += 256) d4[i] = ((const float4*)g_A)[i];
            __syncthreads();
            int nt = w >> 3, jt = w & 7;
            const float* wp = g_Wt1 + (wid*16)*G1 + bid*32 + jt*4;
            const float* ap = smem + (wid*16)*32 + nt*8;
            ull acc[4][4];
#pragma unroll
            for (int i=0;i<4;i++)
#pragma unroll
                for (int j=0;j<4;j++) acc[i][j] = 0ull;
#pragma unroll
            for (int k = 0; k < 16; k++) {
                float4 wv = __ldg((const float4*)wp); wp += G1;
                const ull* a8 = (const ull*)ap; ap += 32;
                ull a0=a8[0], a1=a8[1], a2=a8[2], a3=a8[3];
                ull w0=pack2(wv.x), w1=pack2(wv.y), w2=pack2(wv.z), w3=pack2(wv.w);
                fma2(acc[0][0],w0,a0); fma2(acc[0][1],w0,a1); fma2(acc[0][2],w0,a2); fma2(acc[0][3],w0,a3);
                fma2(acc[1][0],w1,a0); fma2(acc[1][1],w1,a1); fma2(acc[1][2],w1,a2); fma2(acc[1][3],w1,a3);
                fma2(acc[2][0],w2,a0); fma2(acc[2][1],w2,a1); fma2(acc[2][2],w2,a2); fma2(acc[2][3],w2,a3);
                fma2(acc[3][0],w3,a0); fma2(acc[3][1],w3,a1); fma2(acc[3][2],w3,a2); fma2(acc[3][3],w3,a3);
            }
            __syncthreads();
#pragma unroll
            for (int jj=0;jj<4;jj++)
#pragma unroll
                for (int p=0;p<4;p++)
                    *(ull*)&smem[(wid*32 + jt*4+jj)*32 + nt*8 + p*2] = acc[jj][p];
            __syncthreads();
            int u_loc = tid >> 5, n = tid & 31;
            int u_glob = bid*8 + u_loc;
            float G[4];
#pragma unroll
            for (int g = 0; g < 4; g++) {
                int jp = u_glob*4 + g;
                float s = g_Xg2[((size_t)t*G1 + jp)*32 + n];
#pragma unroll
                for (int sp = 0; sp < 3; sp++) s += g_hhp[((size_t)sp*G1 + jp)*32 + n];
#pragma unroll
                for (int q = 0; q < 8; q++) s += smem[(q*32 + u_loc*4 + g)*32 + n];
                G[g] = s;
            }
            float i_ = sigm(G[0]), f_ = sigm(G[1]), gg = tanhf(G[2]), o_ = sigm(G[3]);
            float c = f_*g_c1[u_glob*32 + n] + i_*gg;
            g_c1[u_glob*32 + n] = c;
            float h = o_*tanhf(c);
            af_write(u_glob >> 4, n, u_glob & 15, h);   // h1 fragment (ktA 0..63)
        }
        gbarN(&g_arrive, &g_gen, NBLK);

        if (bid < NB) {
            // ===== P2: LSTM2 gates via mma, mt = bid (16 j'), warps split 72 kt =====
            {
                float d[4][4];
#pragma unroll
                for (int i=0;i<4;i++)
#pragma unroll
                    for (int j=0;j<4;j++) d[i][j]=0.f;
                const uint4* Ah = g_W2f_hi + ((size_t)bid*72 + wid*9)*32 + w;
                const uint4* Al = g_W2f_lo + ((size_t)bid*72 + wid*9)*32 + w;
                const ull* Bh = (const ull*)g_Af_hi;
                const ull* Bl = (const ull*)g_Af_lo;
                for (int kt = wid*9; kt < wid*9 + 9; kt++) {
                    uint4 ah = __ldg(Ah); Ah += 32;
                    uint4 al = __ldg(Al); Al += 32;
                    int boff = kt*128 + w;
#pragma unroll
                    for (int n8 = 0; n8 < 4; n8++) {
                        ull bh = __ldg(Bh + boff + n8*32);
                        ull bl = __ldg(Bl + boff + n8*32);
                        unsigned bh0=(unsigned)bh, bh1=(unsigned)(bh>>32);
                        unsigned bl0=(unsigned)bl, bl1=(unsigned)(bl>>32);
                        mma16816(d[n8], ah, bh0, bh1);
                        mma16816(d[n8], ah, bl0, bl1);
                        mma16816(d[n8], al, bh0, bh1);
                    }
                }
                int jl0 = w >> 2, c0 = (w & 3)*2;
#pragma unroll
                for (int n8 = 0; n8 < 4; n8++) {
                    *(float2*)&smem[wid*512 + jl0*32 + n8*8 + c0]     = make_float2(d[n8][0], d[n8][1]);
                    *(float2*)&smem[wid*512 + (jl0+8)*32 + n8*8 + c0] = make_float2(d[n8][2], d[n8][3]);
                }
                __syncthreads();
                for (int o = tid; o < 512; o += 256) {
                    int jl = o >> 5, n = o & 31;
                    float s = 0.f;
#pragma unroll
                    for (int q = 0; q < 8; q++) s += smem[q*512 + o];
                    g_g2T[n*512 + bid*16 + jl] = s;
                }
                __syncthreads();
            }
            gbarN(&g_arr2, &g_gen2, 32);

            // ===== P3: cell2 + attention, n = bid =====
            int n = bid;
            if (tid < 128) {
                int u = tid;
                float4 gv = *(const float4*)&g_g2T[n*512 + u*4];
                float i_ = sigm(gv.x + b_ih2[u]       + b_hh2[u]);
                float f_ = sigm(gv.y + b_ih2[128+u]   + b_hh2[128+u]);
                float gg = tanhf(gv.z + b_ih2[256+u]  + b_hh2[256+u]);
                float o_ = sigm(gv.w + b_ih2[384+u]   + b_hh2[384+u]);
                float c = f_*g_c2[n*128 + u] + i_*gg;
                g_c2[n*128 + u] = c;
                float h = o_*tanhf(c);
                sh2[u] = h;
                af_write(64 + (u >> 4), n, u & 15, h);   // h2 fragment (ktA 64..71)
                g_h2ctx[((size_t)t*32 + n)*256 + u] = h;
            }
            __syncthreads();
            int len = elens[n];
            float4 hv = ((const float4*)sh2)[w];
            for (int tb = wid*4; tb < TE; tb += 32) {
                float p[4];
#pragma unroll
                for (int i=0;i<4;i++) {
                    float4 kv = ((const float4*)&key[((size_t)n*TE + tb + i)*KSZ])[w];
                    p[i] = kv.x*hv.x + kv.y*hv.y + kv.z*hv.z + kv.w*hv.w;
                }
#pragma unroll
                for (int sh = 16; sh > 0; sh >>= 1) {
#pragma unroll
                    for (int i=0;i<4;i++) p[i] += __shfl_xor_sync(0xffffffffu, p[i], sh);
                }
                if (w < 4) es[tb + w] = (tb + w >= len) ? -1.0e9f : p[w];
            }
            __syncthreads();
            float m = fmaxf(es[tid], es[tid + 256]);
            red[tid] = m;
            __syncthreads();
            for (int st = 128; st > 0; st >>= 1) {
                if (tid < st) red[tid] = fmaxf(red[tid], red[tid + st]);
                __syncthreads();
            }
            float mx = red[0];
            __syncthreads();
            float p0 = expf(es[tid] - mx);
            float p1 = expf(es[tid + 256] - mx);
            es[tid] = p0; es[tid + 256] = p1;
            red[tid] = p0 + p1;
            __syncthreads();
            for (int st = 128; st > 0; st >>= 1) {
                if (tid < st) red[tid] += red[tid + st];
                __syncthreads();
            }
            float inv = 1.0f / red[0];
            int v = tid & 127, half = tid >> 7;
            float acc = 0.f;
            int tbase = half * 256;
#pragma unroll 4
            for (int te = tbase; te < tbase + 256; te++)
                acc += es[te] * values[((size_t)n*TE + te)*128 + v];
            cs[half][v] = acc;
            __syncthreads();
            if (tid < 128) {
                float ctx = (cs[0][tid] + cs[1][tid]) * inv;
                g_A[tid*32 + n] = ctx;
                g_h2ctx[((size_t)t*32 + n)*256 + 128 + tid] = ctx;
            }
        } else if (t < LD-1) {
            // ===== hh-GEMM (t+1) via mma: blocks 32..127 = 32 jc x 3 ks =====
            int idx = bid - 32;
            int jc = idx / 3, ks3 = idx - jc*3;
            int kt0 = (ks3==0) ? 0 : ((ks3==1) ? 22 : 43);
            int nkt = (ks3==0) ? 22 : 21;
            int mt = jc*8 + wid;
            float d[4][4];
#pragma unroll
            for (int i=0;i<4;i++)
#pragma unroll
                for (int j=0;j<4;j++) d[i][j]=0.f;
            const uint4* Ah = g_W1f_hi + ((size_t)mt*64 + kt0)*32 + w;
            const uint4* Al = g_W1f_lo + ((size_t)mt*64 + kt0)*32 + w;
            const ull* Bh = (const ull*)g_Af_hi;
            const ull* Bl = (const ull*)g_Af_lo;
            for (int kt = kt0; kt < kt0 + nkt; kt++) {
                uint4 ah = __ldg(Ah); Ah += 32;
                uint4 al = __ldg(Al); Al += 32;
                int boff = kt*128 + w;
#pragma unroll
                for (int n8 = 0; n8 < 4; n8++) {
                    ull bh = __ldg(Bh + boff + n8*32);
                    ull bl = __ldg(Bl + boff + n8*32);
                    unsigned bh0=(unsigned)bh, bh1=(unsigned)(bh>>32);
                    unsigned bl0=(unsigned)bl, bl1=(unsigned)(bl>>32);
                    mma16816(d[n8], ah, bh0, bh1);
                    mma16816(d[n8], ah, bl0, bl1);
                    mma16816(d[n8], al, bh0, bh1);
                }
            }
            int r0 = mt*16 + (w >> 2);
            int c0 = (w & 3)*2;
#pragma unroll
            for (int n8 = 0; n8 < 4; n8++) {
                *(float2*)&g_hhp[((size_t)ks3*G1 + r0)*32 + n8*8 + c0]     = make_float2(d[n8][0], d[n8][1]);
                *(float2*)&g_hhp[((size_t)ks3*G1 + r0+8)*32 + n8*8 + c0]   = make_float2(d[n8][2], d[n8][3]);
            }
        }
        gbarN(&g_arrive, &g_gen, NBLK);
    }
}

// ---------------- launch ----------------
extern "C" void kernel_launch(void* const* d_in, const int* in_sizes, int n_in,
                              void* d_out, int out_size)
{
    const float* key    = (const float*)d_in[0];
    const float* values = (const float*)d_in[1];
    const int*   elens  = (const int*)  d_in[2];
    const int*   text   = (const int*)  d_in[3];
    const float* emb    = (const float*)d_in[4];
    const float* W_ih1  = (const float*)d_in[5];
    const float* W_hh1  = (const float*)d_in[6];
    const float* b_ih1  = (const float*)d_in[7];
    const float* b_hh1  = (const float*)d_in[8];
    const float* W_ih2  = (const float*)d_in[9];
    const float* W_hh2  = (const float*)d_in[10];
    const float* b_ih2  = (const float*)d_in[11];
    const float* b_hh2  = (const float*)d_in[12];
    const float* W_out  = (const float*)d_in[13];
    const float* b_out  = (const float*)d_in[14];
    float* out = (float*)d_out;

    cudaFuncSetAttribute(kPersist, cudaFuncAttributeMaxDynamicSharedMemorySize, 32768);

    kInit<<<LD*NB + 1984, 256>>>(text, emb, values);
    kPack<<<1152, 256>>>(W_ih1, W_hh1);
    kPackF<<<2336, 256>>>(W_hh1, W_ih2, W_hh2);

    float* gXg; cudaGetSymbolAddress((void**)&gXg, g_Xg);
    float* gX;  cudaGetSymbolAddress((void**)&gX, g_X);
    kGemmBig<384,0><<<dim3(G1/64, (LD*NB)/128), 256>>>(gX, W_ih1, b_ih1, b_hh1, gXg, G1);
    kXgT<<<4096, 256>>>();

    kPersist<<<NBLK, 256, 32768>>>(key, values, elens, b_ih2, b_hh2);

    float* gHC; cudaGetSymbolAddress((void**)&gHC, g_h2ctx);
    kGemmBig<256,1><<<dim3(VV/64, (LD*NB)/128), 256>>>(gHC, W_out, b_out, (const float*)0, out, VV);
}

// round 10
// speedup vs baseline: 2.1846x; 1.3275x over previous
#include <cuda_runtime.h>
#include <cuda_bf16.h>
#include <math.h>

#define NB 32
#define TE 512
#define LD 128
#define VV 8000
#define HH 1024
#define KSZ 128
#define G1 4096
#define KT 1152
#define NBLK 128
typedef unsigned long long ull;

__device__ __align__(16) float g_X[(LD*NB)*256];
__device__ __align__(16) float g_Xg2[(size_t)LD*G1*NB];
__device__ __align__(16) float g_Wt1[128*G1];       // ctx part k-major [k][j']
__device__ __align__(16) float g_A[KT*NB];          // ctx fp32 [k][n] (k<128 used)
__device__ __align__(16) float g_c1[HH*NB];
__device__ __align__(16) float g_c2[NB*KSZ];
__device__ __align__(16) float g_hhp[3*G1*NB];
__device__ __align__(16) float g_g2T[NB*512];
__device__ __align__(16) float g_h2ctx[(LD*NB)*256];
// persist-weights fragments (hi/lo bf16 split)
__device__ uint4 g_W1f_hi[524288], g_W1f_lo[524288];   // 256 mt x 64 kt
__device__ uint4 g_W2f_hi[73728],  g_W2f_lo[73728];    // 32 mt x 72 kt
// activation B-fragments for persist
__device__ unsigned g_Af_hi[18432], g_Af_lo[18432];
// big-GEMM weight fragments
__device__ uint4 g_WXf_hi[131072], g_WXf_lo[131072];   // 256 mt x 16 kt (W_ih1 x-part, jp rows)
__device__ uint4 g_WOf_hi[256000], g_WOf_lo[256000];   // 500 mt x 16 kt (W_out)
// big-GEMM activation fragments: [kt 16][n8 512][lane 32] (ull = 2 regs)
__device__ ull g_Aaf_hi[262144], g_Aaf_lo[262144];
// barriers
__device__ unsigned g_grp[8*32], g_mst = 0;
__device__ unsigned g_grp2[4*32], g_mst2 = 0;
__device__ unsigned g_gen = 0, g_gen2 = 0;

__device__ __forceinline__ float sigm(float x){ return 1.0f/(1.0f + expf(-x)); }
__device__ __forceinline__ unsigned ldv(const unsigned* p){
    unsigned v; asm volatile("ld.volatile.global.u32 %0, [%1];" : "=r"(v) : "l"(p)); return v; }
__device__ __forceinline__ void stv(unsigned* p, unsigned v){
    asm volatile("st.volatile.global.u32 [%0], %1;" :: "l"(p), "r"(v)); }

__device__ __forceinline__ void gbar(int bid)
{
    __syncthreads();
    if (threadIdx.x == 0) {
        __threadfence();
        unsigned gen = ldv(&g_gen);
        if (atomicAdd(&g_grp[(bid & 7)*32], 1u) == 15u) {
            if (atomicAdd(&g_mst, 1u) == 7u) {
                for (int c = 0; c < 8; c++) stv(&g_grp[c*32], 0u);
                stv(&g_mst, 0u);
                __threadfence();
                stv(&g_gen, gen + 1u);
            }
        }
        while (ldv(&g_gen) == gen) { }
        __threadfence();
    }
    __syncthreads();
}
__device__ __forceinline__ void gbar32(int bid)
{
    __syncthreads();
    if (threadIdx.x == 0) {
        __threadfence();
        unsigned gen = ldv(&g_gen2);
        if (atomicAdd(&g_grp2[(bid & 3)*32], 1u) == 7u) {
            if (atomicAdd(&g_mst2, 1u) == 3u) {
                for (int c = 0; c < 4; c++) stv(&g_grp2[c*32], 0u);
                stv(&g_mst2, 0u);
                __threadfence();
                stv(&g_gen2, gen + 1u);
            }
        }
        while (ldv(&g_gen2) == gen) { }
        __threadfence();
    }
    __syncthreads();
}

__device__ __forceinline__ void fma2(ull& d, ull a, ull b){
    asm("fma.rn.f32x2 %0, %1, %2, %0;" : "+l"(d) : "l"(a), "l"(b));
}
__device__ __forceinline__ ull pack2(float x){
    ull d; unsigned u = __float_as_uint(x);
    asm("mov.b64 %0, {%1, %1};" : "=l"(d) : "r"(u));
    return d;
}

__device__ __forceinline__ void mma16816(float* d, uint4 a, unsigned b0, unsigned b1){
    asm("mma.sync.aligned.m16n8k16.row.col.f32.bf16.bf16.f32 "
        "{%0,%1,%2,%3}, {%4,%5,%6,%7}, {%8,%9}, {%0,%1,%2,%3};"
        : "+f"(d[0]), "+f"(d[1]), "+f"(d[2]), "+f"(d[3])
        : "r"(a.x), "r"(a.y), "r"(a.z), "r"(a.w), "r"(b0), "r"(b1));
}
__device__ __forceinline__ unsigned pbf(float e0, float e1, float* r0, float* r1){
    __nv_bfloat16 h0 = __float2bfloat16(e0), h1 = __float2bfloat16(e1);
    *r0 = e0 - __bfloat162float(h0);
    *r1 = e1 - __bfloat162float(h1);
    return (unsigned)__bfloat16_as_ushort(h0) | ((unsigned)__bfloat16_as_ushort(h1) << 16);
}
__device__ __forceinline__ unsigned pklo(float a, float b){
    return (unsigned)__bfloat16_as_ushort(__float2bfloat16(a)) |
           ((unsigned)__bfloat16_as_ushort(__float2bfloat16(b)) << 16);
}
__device__ __forceinline__ void af_write(int ktA, int n, int kp, float v){
    __nv_bfloat16 bh = __float2bfloat16(v);
    __nv_bfloat16 bl = __float2bfloat16(v - __bfloat162float(bh));
    int n8 = n >> 3, np = n & 7;
    int lane = np*4 + ((kp & 7) >> 1);
    int reg = kp >> 3, half = kp & 1;
    size_t bi = ((((size_t)ktA*4 + n8)*32 + lane)*2 + reg)*2 + half;
    ((__nv_bfloat16*)g_Af_hi)[bi] = bh;
    ((__nv_bfloat16*)g_Af_lo)[bi] = bl;
}

// ---------------- init ----------------
__global__ __launch_bounds__(256) void kInit(const int* __restrict__ text,
                                             const float* __restrict__ emb,
                                             const float* __restrict__ values)
{
    int b = blockIdx.x, tid = threadIdx.x;
    if (b < LD*NB) {
        int t = b >> 5, n = b & 31;
        int idx = (t == 0) ? 1 : text[n*LD + (t-1)];
        g_X[b*256 + tid] = emb[idx*256 + tid];
    } else {
        int i = (b - LD*NB)*256 + tid;
        if      (i < 32768) g_c1[i] = 0.f;
        else if (i < 36864) g_c2[i - 32768] = 0.f;
        else if (i < 40960) { int u = i - 36864; int k = u >> 5, n = u & 31;
                              g_A[k*32 + n] = values[n*(TE*128) + k]; }
        else if (i < 434176) g_hhp[i - 40960] = 0.f;
        else { int z = i - 434176;
               if (z < 18432) g_Af_hi[z] = 0u;
               else if (z < 36864) g_Af_lo[z - 18432] = 0u; }
    }
}

// ---------------- ctx-part of W1 to k-major fp32 ----------------
__global__ __launch_bounds__(256) void kPack(const float* __restrict__ W_ih1)
{
    __shared__ float s[32][129];
    int ub = blockIdx.x, tid = threadIdx.x;
    int r = tid >> 3, c0 = (tid & 7) * 16;
    int g = r & 3, ul = r >> 2;
    int j = g*1024 + ub*8 + ul;
    const float* src = W_ih1 + j*384 + 256;
    for (int q = 0; q < 16; q += 4) {
        float4 v = *(const float4*)&src[c0+q];
        s[r][c0+q+0] = v.x; s[r][c0+q+1] = v.y;
        s[r][c0+q+2] = v.z; s[r][c0+q+3] = v.w;
    }
    __syncthreads();
    int rr = tid & 31, klg = tid >> 5;
    for (int kl = klg*16; kl < klg*16 + 16; kl++)
        g_Wt1[kl*G1 + ub*32 + rr] = s[rr][kl];
}

// ---------------- persist weight fragments ----------------
__global__ __launch_bounds__(256) void kPackF(const float* __restrict__ W_hh1,
                                              const float* __restrict__ W_ih2,
                                              const float* __restrict__ W_hh2)
{
    int b = blockIdx.x, tid = threadIdx.x, wid = tid >> 5, l = tid & 31;
    if (b < 2048) {
        int tile = b*8 + wid;
        int mt = tile >> 6, kt = tile & 63;
        unsigned hi[4], lo[4];
#pragma unroll
        for (int p = 0; p < 4; p++) {
            int jp = mt*16 + (l>>2) + (p&1)*8;
            int u = jp >> 2, g = jp & 3;
            int k = kt*16 + (l&3)*2 + ((p>>1)&1)*8;
            const float* src = W_hh1 + (size_t)(g*1024+u)*1024 + k;
            float r0, r1;
            hi[p] = pbf(src[0], src[1], &r0, &r1);
            lo[p] = pklo(r0, r1);
        }
        g_W1f_hi[(size_t)tile*32 + l] = make_uint4(hi[0],hi[1],hi[2],hi[3]);
        g_W1f_lo[(size_t)tile*32 + l] = make_uint4(lo[0],lo[1],lo[2],lo[3]);
    } else {
        int tile = (b - 2048)*8 + wid;
        if (tile >= 2304) return;
        int mt = tile / 72, kt = tile - mt*72;
        unsigned hi[4], lo[4];
#pragma unroll
        for (int p = 0; p < 4; p++) {
            int jp = mt*16 + (l>>2) + (p&1)*8;
            int u = jp >> 2, g = jp & 3;
            int k = kt*16 + (l&3)*2 + ((p>>1)&1)*8;
            const float* src = (k < 1024) ? (W_ih2 + (size_t)(g*128+u)*1024 + k)
                                          : (W_hh2 + (size_t)(g*128+u)*128 + (k - 1024));
            float r0, r1;
            hi[p] = pbf(src[0], src[1], &r0, &r1);
            lo[p] = pklo(r0, r1);
        }
        g_W2f_hi[(size_t)tile*32 + l] = make_uint4(hi[0],hi[1],hi[2],hi[3]);
        g_W2f_lo[(size_t)tile*32 + l] = make_uint4(lo[0],lo[1],lo[2],lo[3]);
    }
}

// ---------------- big-GEMM weight fragments (WX jp-rows, WO direct rows) ----------------
__global__ __launch_bounds__(256) void kPackW(const float* __restrict__ W_ih1,
                                              const float* __restrict__ W_out)
{
    int tile = blockIdx.x*8 + (threadIdx.x >> 5);
    int l = threadIdx.x & 31;
    if (tile < 4096) {
        int mt = tile >> 4, kt = tile & 15;
        unsigned hi[4], lo[4];
#pragma unroll
        for (int p = 0; p < 4; p++) {
            int jp = mt*16 + (l>>2) + (p&1)*8;
            int j = (jp & 3)*1024 + (jp >> 2);
            int k = kt*16 + (l&3)*2 + ((p>>1)&1)*8;
            const float* src = W_ih1 + (size_t)j*384 + k;
            float r0, r1;
            hi[p] = pbf(src[0], src[1], &r0, &r1);
            lo[p] = pklo(r0, r1);
        }
        g_WXf_hi[(size_t)tile*32 + l] = make_uint4(hi[0],hi[1],hi[2],hi[3]);
        g_WXf_lo[(size_t)tile*32 + l] = make_uint4(lo[0],lo[1],lo[2],lo[3]);
    } else {
        int tl = tile - 4096;
        if (tl >= 8000) return;
        int mt = tl >> 4, kt = tl & 15;
        unsigned hi[4], lo[4];
#pragma unroll
        for (int p = 0; p < 4; p++) {
            int j = mt*16 + (l>>2) + (p&1)*8;
            int k = kt*16 + (l&3)*2 + ((p>>1)&1)*8;
            const float* src = W_out + (size_t)j*256 + k;
            float r0, r1;
            hi[p] = pbf(src[0], src[1], &r0, &r1);
            lo[p] = pklo(r0, r1);
        }
        g_WOf_hi[(size_t)tl*32 + l] = make_uint4(hi[0],hi[1],hi[2],hi[3]);
        g_WOf_lo[(size_t)tl*32 + l] = make_uint4(lo[0],lo[1],lo[2],lo[3]);
    }
}

// ---------------- activation B-fragments for big GEMM: A [4096 rows][256] ----------------
__global__ __launch_bounds__(256) void kPackA(const float* __restrict__ A)
{
    int gw = blockIdx.x*8 + (threadIdx.x >> 5);   // 0..8191 = kt*512 + n8
    int l = threadIdx.x & 31;
    int kt = gw >> 9, n8 = gw & 511;
    int n = n8*8 + (l >> 2);
    int k0 = kt*16 + (l & 3)*2;
    const float* src = A + (size_t)n*256;
    float r0, r1, r2, r3;
    unsigned h0 = pbf(src[k0],   src[k0+1], &r0, &r1);
    unsigned h1 = pbf(src[k0+8], src[k0+9], &r2, &r3);
    g_Aaf_hi[(size_t)gw*32 + l] = ((ull)h1 << 32) | h0;
    g_Aaf_lo[(size_t)gw*32 + l] = ((ull)pklo(r2,r3) << 32) | pklo(r0,r1);
}

// ---------------- big mma GEMM: MODE 0 -> g_Xg2 (+b1+b2), MODE 1 -> logits (+b1) ----------------
template<int MODE>
__global__ __launch_bounds__(256) void kMMAW(const uint4* __restrict__ Wh, const uint4* __restrict__ Wl,
                                             const float* __restrict__ bias1, const float* __restrict__ bias2,
                                             float* __restrict__ out, int MT)
{
    int wid = threadIdx.x >> 5, l = threadIdx.x & 31;
    int mt = blockIdx.x*8 + wid;
    if (mt >= MT) return;
    int by = blockIdx.y;
    float d[16][4];
#pragma unroll
    for (int i=0;i<16;i++)
#pragma unroll
        for (int j=0;j<4;j++) d[i][j] = 0.f;
    for (int kt = 0; kt < 16; kt++) {
        uint4 wh = __ldg(Wh + ((size_t)mt*16 + kt)*32 + l);
        uint4 wl = __ldg(Wl + ((size_t)mt*16 + kt)*32 + l);
#pragma unroll
        for (int n8 = 0; n8 < 16; n8++) {
            size_t bi = ((size_t)kt*512 + by*16 + n8)*32 + l;
            ull bh = __ldg(g_Aaf_hi + bi), bl = __ldg(g_Aaf_lo + bi);
            unsigned bh0=(unsigned)bh, bh1=(unsigned)(bh>>32);
            unsigned bl0=(unsigned)bl, bl1=(unsigned)(bl>>32);
            mma16816(d[n8], wh, bh0, bh1);
            mma16816(d[n8], wh, bl0, bl1);
            mma16816(d[n8], wl, bh0, bh1);
        }
    }
    int jr0 = mt*16 + (l >> 2), jr1 = jr0 + 8;
    float b0, b1;
    if (MODE == 0) {
        int j0 = (jr0 & 3)*1024 + (jr0 >> 2), j1 = (jr1 & 3)*1024 + (jr1 >> 2);
        b0 = bias1[j0] + bias2[j0];
        b1 = bias1[j1] + bias2[j1];
    } else {
        b0 = bias1[jr0]; b1 = bias1[jr1];
    }
#pragma unroll
    for (int n8 = 0; n8 < 16; n8++) {
        int r = by*128 + n8*8 + (l & 3)*2;
        int n0 = r & 31, t0 = r >> 5;
        if (MODE == 0) {
            *(float2*)&g_Xg2[((size_t)t0*G1 + jr0)*32 + n0] = make_float2(d[n8][0]+b0, d[n8][1]+b0);
            *(float2*)&g_Xg2[((size_t)t0*G1 + jr1)*32 + n0] = make_float2(d[n8][2]+b1, d[n8][3]+b1);
        } else {
            float* o0 = out + ((size_t)n0*LD + t0)*VV;
            float* o1 = out + ((size_t)(n0+1)*LD + t0)*VV;
            o0[jr0] = d[n8][0] + b0;  o1[jr0] = d[n8][1] + b0;
            o0[jr1] = d[n8][2] + b1;  o1[jr1] = d[n8][3] + b1;
        }
    }
}

// ---------------- persistent decoder ----------------
__global__ __launch_bounds__(256, 1) void kPersist(
    const float* __restrict__ key, const float* __restrict__ values,
    const int* __restrict__ elens,
    const float* __restrict__ b_ih2, const float* __restrict__ b_hh2)
{
    extern __shared__ float smem[];               // 32 KB
    __shared__ __align__(16) float sh2[128];
    __shared__ float es[512];
    __shared__ float red[256];

    int bid = blockIdx.x, tid = threadIdx.x;
    int wid = tid >> 5, w = tid & 31;

    for (int t = 0; t < LD; t++) {
        // ===== P1: ctx GEMM (fp32, K=128) + hh/Xg reduce + cell1 =====
        {
            float4* d4 = (float4*)smem;
            for (int i = tid; i < 1024; i += 256) d4[i] = ((const float4*)g_A)[i];
            __syncthreads();
            int nt = w >> 3, jt = w & 7;
            const float* wp = g_Wt1 + (wid*16)*G1 + bid*32 + jt*4;
            const float* ap = smem + (wid*16)*32 + nt*8;
            ull acc[4][4];
#pragma unroll
            for (int i=0;i<4;i++)
#pragma unroll
                for (int j=0;j<4;j++) acc[i][j] = 0ull;
#pragma unroll
            for (int k = 0; k < 16; k++) {
                float4 wv = __ldg((const float4*)wp); wp += G1;
                const ull* a8 = (const ull*)ap; ap += 32;
                ull a0=a8[0], a1=a8[1], a2=a8[2], a3=a8[3];
                ull w0=pack2(wv.x), w1=pack2(wv.y), w2=pack2(wv.z), w3=pack2(wv.w);
                fma2(acc[0][0],w0,a0); fma2(acc[0][1],w0,a1); fma2(acc[0][2],w0,a2); fma2(acc[0][3],w0,a3);
                fma2(acc[1][0],w1,a0); fma2(acc[1][1],w1,a1); fma2(acc[1][2],w1,a2); fma2(acc[1][3],w1,a3);
                fma2(acc[2][0],w2,a0); fma2(acc[2][1],w2,a1); fma2(acc[2][2],w2,a2); fma2(acc[2][3],w2,a3);
                fma2(acc[3][0],w3,a0); fma2(acc[3][1],w3,a1); fma2(acc[3][2],w3,a2); fma2(acc[3][3],w3,a3);
            }
            __syncthreads();
#pragma unroll
            for (int jj=0;jj<4;jj++)
#pragma unroll
                for (int p=0;p<4;p++)
                    *(ull*)&smem[(wid*32 + jt*4+jj)*32 + nt*8 + p*2] = acc[jj][p];
            __syncthreads();
            int u_loc = tid >> 5, n = tid & 31;
            int u_glob = bid*8 + u_loc;
            float G[4];
#pragma unroll
            for (int g = 0; g < 4; g++) {
                int jp = u_glob*4 + g;
                float s = g_Xg2[((size_t)t*G1 + jp)*32 + n];
#pragma unroll
                for (int sp = 0; sp < 3; sp++) s += g_hhp[((size_t)sp*G1 + jp)*32 + n];
#pragma unroll
                for (int q = 0; q < 8; q++) s += smem[(q*32 + u_loc*4 + g)*32 + n];
                G[g] = s;
            }
            float i_ = sigm(G[0]), f_ = sigm(G[1]), gg = tanhf(G[2]), o_ = sigm(G[3]);
            float c = f_*g_c1[u_glob*32 + n] + i_*gg;
            g_c1[u_glob*32 + n] = c;
            float h = o_*tanhf(c);
            af_write(u_glob >> 4, n, u_glob & 15, h);
        }
        gbar(bid);

        if (bid < NB) {
            // ===== P2: LSTM2 gates via mma =====
            {
                float d[4][4];
#pragma unroll
                for (int i=0;i<4;i++)
#pragma unroll
                    for (int j=0;j<4;j++) d[i][j]=0.f;
                const uint4* Ah = g_W2f_hi + ((size_t)bid*72 + wid*9)*32 + w;
                const uint4* Al = g_W2f_lo + ((size_t)bid*72 + wid*9)*32 + w;
                const ull* Bh = (const ull*)g_Af_hi;
                const ull* Bl = (const ull*)g_Af_lo;
                for (int kt = wid*9; kt < wid*9 + 9; kt++) {
                    uint4 ah = __ldg(Ah); Ah += 32;
                    uint4 al = __ldg(Al); Al += 32;
                    int boff = kt*128 + w;
#pragma unroll
                    for (int n8 = 0; n8 < 4; n8++) {
                        ull bh = __ldg(Bh + boff + n8*32);
                        ull bl = __ldg(Bl + boff + n8*32);
                        unsigned bh0=(unsigned)bh, bh1=(unsigned)(bh>>32);
                        unsigned bl0=(unsigned)bl, bl1=(unsigned)(bl>>32);
                        mma16816(d[n8], ah, bh0, bh1);
                        mma16816(d[n8], ah, bl0, bl1);
                        mma16816(d[n8], al, bh0, bh1);
                    }
                }
                int jl0 = w >> 2, c0 = (w & 3)*2;
#pragma unroll
                for (int n8 = 0; n8 < 4; n8++) {
                    *(float2*)&smem[wid*512 + jl0*32 + n8*8 + c0]     = make_float2(d[n8][0], d[n8][1]);
                    *(float2*)&smem[wid*512 + (jl0+8)*32 + n8*8 + c0] = make_float2(d[n8][2], d[n8][3]);
                }
                __syncthreads();
                for (int o = tid; o < 512; o += 256) {
                    int jl = o >> 5, n = o & 31;
                    float s = 0.f;
#pragma unroll
                    for (int q = 0; q < 8; q++) s += smem[q*512 + o];
                    g_g2T[n*512 + bid*16 + jl] = s;
                }
                __syncthreads();
            }
            gbar32(bid);

            // ===== P3: cell2 + attention, n = bid =====
            int n = bid;
            if (tid < 128) {
                int u = tid;
                float4 gv = *(const float4*)&g_g2T[n*512 + u*4];
                float i_ = sigm(gv.x + b_ih2[u]       + b_hh2[u]);
                float f_ = sigm(gv.y + b_ih2[128+u]   + b_hh2[128+u]);
                float gg = tanhf(gv.z + b_ih2[256+u]  + b_hh2[256+u]);
                float o_ = sigm(gv.w + b_ih2[384+u]   + b_hh2[384+u]);
                float c = f_*g_c2[n*128 + u] + i_*gg;
                g_c2[n*128 + u] = c;
                float h = o_*tanhf(c);
                sh2[u] = h;
                af_write(64 + (u >> 4), n, u & 15, h);
                g_h2ctx[((size_t)t*32 + n)*256 + u] = h;
            }
            __syncthreads();
            int len = elens[n];
            float4 hv = ((const float4*)sh2)[w];
            for (int tb = wid*4; tb < TE; tb += 32) {
                float p[4];
#pragma unroll
                for (int i=0;i<4;i++) {
                    float4 kv = ((const float4*)&key[((size_t)n*TE + tb + i)*KSZ])[w];
                    p[i] = kv.x*hv.x + kv.y*hv.y + kv.z*hv.z + kv.w*hv.w;
                }
#pragma unroll
                for (int sh = 16; sh > 0; sh >>= 1) {
#pragma unroll
                    for (int i=0;i<4;i++) p[i] += __shfl_xor_sync(0xffffffffu, p[i], sh);
                }
                if (w < 4) es[tb + w] = (tb + w >= len) ? -1.0e9f : p[w];
            }
            __syncthreads();
            float m = fmaxf(es[tid], es[tid + 256]);
            red[tid] = m;
            __syncthreads();
            for (int st = 128; st > 0; st >>= 1) {
                if (tid < st) red[tid] = fmaxf(red[tid], red[tid + st]);
                __syncthreads();
            }
            float mx = red[0];
            __syncthreads();
            float p0 = expf(es[tid] - mx);
            float p1 = expf(es[tid + 256] - mx);
            es[tid] = p0; es[tid + 256] = p1;
            red[tid] = p0 + p1;
            __syncthreads();
            for (int st = 128; st > 0; st >>= 1) {
                if (tid < st) red[tid] += red[tid + st];
                __syncthreads();
            }
            float inv = 1.0f / red[0];
            // vectorized context: warp = te-group of 64, lanes = 32 float4 v-quads
            {
                float4 a4 = make_float4(0.f,0.f,0.f,0.f);
                const float4* vp = (const float4*)values + ((size_t)n*TE + wid*64)*32 + w;
#pragma unroll 4
                for (int te = 0; te < 64; te++) {
                    float e = es[wid*64 + te];
                    float4 v = __ldg(vp); vp += 32;
                    a4.x += e*v.x; a4.y += e*v.y; a4.z += e*v.z; a4.w += e*v.w;
                }
                *(float4*)&smem[wid*128 + w*4] = a4;
            }
            __syncthreads();
            if (tid < 128) {
                float s = 0.f;
#pragma unroll
                for (int g = 0; g < 8; g++) s += smem[g*128 + tid];
                float ctx = s * inv;
                g_A[tid*32 + n] = ctx;
                g_h2ctx[((size_t)t*32 + n)*256 + 128 + tid] = ctx;
            }
            __syncthreads();
        } else if (t < LD-1) {
            // ===== hh-GEMM (t+1) via mma: blocks 32..127 = 32 jc x 3 ks =====
            int idx = bid - 32;
            int jc = idx / 3, ks3 = idx - jc*3;
            int kt0 = (ks3==0) ? 0 : ((ks3==1) ? 22 : 43);
            int nkt = (ks3==0) ? 22 : 21;
            int mt = jc*8 + wid;
            float d[4][4];
#pragma unroll
            for (int i=0;i<4;i++)
#pragma unroll
                for (int j=0;j<4;j++) d[i][j]=0.f;
            const uint4* Ah = g_W1f_hi + ((size_t)mt*64 + kt0)*32 + w;
            const uint4* Al = g_W1f_lo + ((size_t)mt*64 + kt0)*32 + w;
            const ull* Bh = (const ull*)g_Af_hi;
            const ull* Bl = (const ull*)g_Af_lo;
            for (int kt = kt0; kt < kt0 + nkt; kt++) {
                uint4 ah = __ldg(Ah); Ah += 32;
                uint4 al = __ldg(Al); Al += 32;
                int boff = kt*128 + w;
#pragma unroll
                for (int n8 = 0; n8 < 4; n8++) {
                    ull bh = __ldg(Bh + boff + n8*32);
                    ull bl = __ldg(Bl + boff + n8*32);
                    unsigned bh0=(unsigned)bh, bh1=(unsigned)(bh>>32);
                    unsigned bl0=(unsigned)bl, bl1=(unsigned)(bl>>32);
                    mma16816(d[n8], ah, bh0, bh1);
                    mma16816(d[n8], ah, bl0, bl1);
                    mma16816(d[n8], al, bh0, bh1);
                }
            }
            int r0 = mt*16 + (w >> 2);
            int c0 = (w & 3)*2;
#pragma unroll
            for (int n8 = 0; n8 < 4; n8++) {
                *(float2*)&g_hhp[((size_t)ks3*G1 + r0)*32 + n8*8 + c0]   = make_float2(d[n8][0], d[n8][1]);
                *(float2*)&g_hhp[((size_t)ks3*G1 + r0+8)*32 + n8*8 + c0] = make_float2(d[n8][2], d[n8][3]);
            }
        }
        gbar(bid);
    }
}

// ---------------- launch ----------------
extern "C" void kernel_launch(void* const* d_in, const int* in_sizes, int n_in,
                              void* d_out, int out_size)
{
    const float* key    = (const float*)d_in[0];
    const float* values = (const float*)d_in[1];
    const int*   elens  = (const int*)  d_in[2];
    const int*   text   = (const int*)  d_in[3];
    const float* emb    = (const float*)d_in[4];
    const float* W_ih1  = (const float*)d_in[5];
    const float* W_hh1  = (const float*)d_in[6];
    const float* b_ih1  = (const float*)d_in[7];
    const float* b_hh1  = (const float*)d_in[8];
    const float* W_ih2  = (const float*)d_in[9];
    const float* W_hh2  = (const float*)d_in[10];
    const float* b_ih2  = (const float*)d_in[11];
    const float* b_hh2  = (const float*)d_in[12];
    const float* W_out  = (const float*)d_in[13];
    const float* b_out  = (const float*)d_in[14];
    float* out = (float*)d_out;

    cudaFuncSetAttribute(kPersist, cudaFuncAttributeMaxDynamicSharedMemorySize, 32768);

    kInit<<<LD*NB + 1840, 256>>>(text, emb, values);
    kPack<<<128, 256>>>(W_ih1);
    kPackF<<<2336, 256>>>(W_hh1, W_ih2, W_hh2);
    kPackW<<<1512, 256>>>(W_ih1, W_out);

    float* gX; cudaGetSymbolAddress((void**)&gX, g_X);
    kPackA<<<1024, 256>>>(gX);
    uint4 *wxh, *wxl, *woh, *wol;
    cudaGetSymbolAddress((void**)&wxh, g_WXf_hi);
    cudaGetSymbolAddress((void**)&wxl, g_WXf_lo);
    cudaGetSymbolAddress((void**)&woh, g_WOf_hi);
    cudaGetSymbolAddress((void**)&wol, g_WOf_lo);
    kMMAW<0><<<dim3(32,32), 256>>>(wxh, wxl, b_ih1, b_hh1, (float*)0, 256);

    kPersist<<<NBLK, 256, 32768>>>(key, values, elens, b_ih2, b_hh2);

    float* gHC; cudaGetSymbolAddress((void**)&gHC, g_h2ctx);
    kPackA<<<1024, 256>>>(gHC);
    kMMAW<1><<<dim3(63,32), 256>>>(woh, wol, b_out, (const float*)0, out, 500);
}

// round 13
// speedup vs baseline: 2.3917x; 1.0948x over previous
#include <cuda_runtime.h>
#include <cuda_bf16.h>
#include <math.h>

#define NB 32
#define TE 512
#define LD 128
#define VV 8000
#define HH 1024
#define KSZ 128
#define G1 4096
#define KT 1152
#define NBLK 128
typedef unsigned long long ull;

__device__ __align__(16) float g_X[(LD*NB)*256];
__device__ __align__(16) float g_Xg2[(size_t)LD*G1*NB];
__device__ __align__(16) float g_Wt1[128*G1];       // ctx part k-major [k][j']
__device__ __align__(16) float g_A[128*NB];         // ctx fp32 [k][n]
__device__ __align__(16) float g_c1[HH*NB];
__device__ __align__(16) float g_c2[2*NB*KSZ];      // double buffered
__device__ __align__(16) float g_hhp[3*G1*NB];
__device__ __align__(16) float g_g2T[NB*512];
__device__ __align__(16) float g_esG[NB*512];
__device__ __align__(16) float g_h2ctx[(LD*NB)*256];
__device__ uint4 g_W1f_hi[524288], g_W1f_lo[524288];
__device__ uint4 g_W2f_hi[73728],  g_W2f_lo[73728];
__device__ unsigned g_Af_hi[18432], g_Af_lo[18432];
__device__ uint4 g_WXf_hi[131072], g_WXf_lo[131072];
__device__ uint4 g_WOf_hi[256000], g_WOf_lo[256000];
__device__ ull g_Aaf_hi[262144], g_Aaf_lo[262144];
__device__ unsigned g_arr = 0, g_gen = 0;

__device__ __forceinline__ float sigm(float x){ return 1.0f/(1.0f + expf(-x)); }
__device__ __forceinline__ unsigned ldv(const unsigned* p){
    unsigned v; asm volatile("ld.volatile.global.u32 %0, [%1];" : "=r"(v) : "l"(p)); return v; }
__device__ __forceinline__ void stv(unsigned* p, unsigned v){
    asm volatile("st.volatile.global.u32 [%0], %1;" :: "l"(p), "r"(v)); }

__device__ __forceinline__ void gbar()
{
    __syncthreads();
    if (threadIdx.x == 0) {
        __threadfence();
        unsigned gen = ldv(&g_gen);
        if (atomicAdd(&g_arr, 1u) == NBLK - 1u) {
            stv(&g_arr, 0u);
            __threadfence();
            stv(&g_gen, gen + 1u);
        } else {
            while (ldv(&g_gen) == gen) __nanosleep(32);
        }
        __threadfence();
    }
    __syncthreads();
}

__device__ __forceinline__ void fma2(ull& d, ull a, ull b){
    asm("fma.rn.f32x2 %0, %1, %2, %0;" : "+l"(d) : "l"(a), "l"(b));
}
__device__ __forceinline__ ull pack2(float x){
    ull d; unsigned u = __float_as_uint(x);
    asm("mov.b64 %0, {%1, %1};" : "=l"(d) : "r"(u));
    return d;
}
__device__ __forceinline__ uint4 ldcg4(const uint4* p){
    uint4 v; asm("ld.global.cg.v4.u32 {%0,%1,%2,%3}, [%4];"
                 : "=r"(v.x),"=r"(v.y),"=r"(v.z),"=r"(v.w) : "l"(p)); return v; }
__device__ __forceinline__ ull ldcg8(const ull* p){
    ull v; asm("ld.global.cg.u64 %0, [%1];" : "=l"(v) : "l"(p)); return v; }
__device__ __forceinline__ float ldcgf(const float* p){
    float v; asm("ld.global.cg.f32 %0, [%1];" : "=f"(v) : "l"(p)); return v; }

__device__ __forceinline__ void mma16816(float* d, uint4 a, unsigned b0, unsigned b1){
    asm("mma.sync.aligned.m16n8k16.row.col.f32.bf16.bf16.f32 "
        "{%0,%1,%2,%3}, {%4,%5,%6,%7}, {%8,%9}, {%0,%1,%2,%3};"
        : "+f"(d[0]), "+f"(d[1]), "+f"(d[2]), "+f"(d[3])
        : "r"(a.x), "r"(a.y), "r"(a.z), "r"(a.w), "r"(b0), "r"(b1));
}
__device__ __forceinline__ unsigned pbf(float e0, float e1, float* r0, float* r1){
    __nv_bfloat16 h0 = __float2bfloat16(e0), h1 = __float2bfloat16(e1);
    *r0 = e0 - __bfloat162float(h0);
    *r1 = e1 - __bfloat162float(h1);
    return (unsigned)__bfloat16_as_ushort(h0) | ((unsigned)__bfloat16_as_ushort(h1) << 16);
}
__device__ __forceinline__ unsigned pklo(float a, float b){
    return (unsigned)__bfloat16_as_ushort(__float2bfloat16(a)) |
           ((unsigned)__bfloat16_as_ushort(__float2bfloat16(b)) << 16);
}
__device__ __forceinline__ void af_write(int ktA, int n, int kp, float v){
    __nv_bfloat16 bh = __float2bfloat16(v);
    __nv_bfloat16 bl = __float2bfloat16(v - __bfloat162float(bh));
    int n8 = n >> 3, np = n & 7;
    int lane = np*4 + ((kp & 7) >> 1);
    int reg = kp >> 3, half = kp & 1;
    size_t bi = ((((size_t)ktA*4 + n8)*32 + lane)*2 + reg)*2 + half;
    ((__nv_bfloat16*)g_Af_hi)[bi] = bh;
    ((__nv_bfloat16*)g_Af_lo)[bi] = bl;
}

// ---------------- init ----------------
__global__ __launch_bounds__(256) void kInit(const int* __restrict__ text,
                                             const float* __restrict__ emb,
                                             const float* __restrict__ values)
{
    int b = blockIdx.x, tid = threadIdx.x;
    if (b < LD*NB) {
        int t = b >> 5, n = b & 31;
        int idx = (t == 0) ? 1 : text[n*LD + (t-1)];
        g_X[b*256 + tid] = emb[idx*256 + tid];
    } else {
        int i = (b - LD*NB)*256 + tid;
        if      (i < 32768) g_c1[i] = 0.f;
        else if (i < 40960) g_c2[i - 32768] = 0.f;
        else if (i < 45056) { int u = i - 40960; int k = u >> 5, n = u & 31;
                              g_A[k*32 + n] = values[n*(TE*128) + k]; }
        else if (i < 438272) g_hhp[i - 45056] = 0.f;
        else { int z = i - 438272;
               if (z < 18432) g_Af_hi[z] = 0u;
               else if (z < 36864) g_Af_lo[z - 18432] = 0u; }
    }
}

// ---------------- all packing in one kernel ----------------
__global__ __launch_bounds__(256) void kPackAll(const float* __restrict__ W_ih1,
                                                const float* __restrict__ W_hh1,
                                                const float* __restrict__ W_ih2,
                                                const float* __restrict__ W_hh2,
                                                const float* __restrict__ W_out)
{
    __shared__ float s[32][129];
    int b = blockIdx.x, tid = threadIdx.x, wid = tid >> 5, l = tid & 31;
    if (b < 128) {
        int ub = b;
        int r = tid >> 3, c0 = (tid & 7) * 16;
        int g = r & 3, ul = r >> 2;
        int j = g*1024 + ub*8 + ul;
        const float* src = W_ih1 + j*384 + 256;
        for (int q = 0; q < 16; q += 4) {
            float4 v = *(const float4*)&src[c0+q];
            s[r][c0+q+0] = v.x; s[r][c0+q+1] = v.y;
            s[r][c0+q+2] = v.z; s[r][c0+q+3] = v.w;
        }
        __syncthreads();
        int rr = tid & 31, klg = tid >> 5;
        for (int kl = klg*16; kl < klg*16 + 16; kl++)
            g_Wt1[kl*G1 + ub*32 + rr] = s[rr][kl];
    } else if (b < 2464) {
        int bb = b - 128;
        if (bb < 2048) {
            int tile = bb*8 + wid;
            int mt = tile >> 6, kt = tile & 63;
            unsigned hi[4], lo[4];
#pragma unroll
            for (int p = 0; p < 4; p++) {
                int jp = mt*16 + (l>>2) + (p&1)*8;
                int u = jp >> 2, g = jp & 3;
                int k = kt*16 + (l&3)*2 + ((p>>1)&1)*8;
                const float* src = W_hh1 + (size_t)(g*1024+u)*1024 + k;
                float r0, r1;
                hi[p] = pbf(src[0], src[1], &r0, &r1);
                lo[p] = pklo(r0, r1);
            }
            g_W1f_hi[(size_t)tile*32 + l] = make_uint4(hi[0],hi[1],hi[2],hi[3]);
            g_W1f_lo[(size_t)tile*32 + l] = make_uint4(lo[0],lo[1],lo[2],lo[3]);
        } else {
            int tile = (bb - 2048)*8 + wid;
            if (tile >= 2304) return;
            int mt = tile / 72, kt = tile - mt*72;
            unsigned hi[4], lo[4];
#pragma unroll
            for (int p = 0; p < 4; p++) {
                int jp = mt*16 + (l>>2) + (p&1)*8;
                int u = jp >> 2, g = jp & 3;
                int k = kt*16 + (l&3)*2 + ((p>>1)&1)*8;
                const float* src = (k < 1024) ? (W_ih2 + (size_t)(g*128+u)*1024 + k)
                                              : (W_hh2 + (size_t)(g*128+u)*128 + (k - 1024));
                float r0, r1;
                hi[p] = pbf(src[0], src[1], &r0, &r1);
                lo[p] = pklo(r0, r1);
            }
            g_W2f_hi[(size_t)tile*32 + l] = make_uint4(hi[0],hi[1],hi[2],hi[3]);
            g_W2f_lo[(size_t)tile*32 + l] = make_uint4(lo[0],lo[1],lo[2],lo[3]);
        }
    } else if (b < 3976) {
        int tile = (b - 2464)*8 + wid;
        if (tile < 4096) {
            int mt = tile >> 4, kt = tile & 15;
            unsigned hi[4], lo[4];
#pragma unroll
            for (int p = 0; p < 4; p++) {
                int jp = mt*16 + (l>>2) + (p&1)*8;
                int j = (jp & 3)*1024 + (jp >> 2);
                int k = kt*16 + (l&3)*2 + ((p>>1)&1)*8;
                const float* src = W_ih1 + (size_t)j*384 + k;
                float r0, r1;
                hi[p] = pbf(src[0], src[1], &r0, &r1);
                lo[p] = pklo(r0, r1);
            }
            g_WXf_hi[(size_t)tile*32 + l] = make_uint4(hi[0],hi[1],hi[2],hi[3]);
            g_WXf_lo[(size_t)tile*32 + l] = make_uint4(lo[0],lo[1],lo[2],lo[3]);
        } else {
            int tl = tile - 4096;
            if (tl >= 8000) return;
            int mt = tl >> 4, kt = tl & 15;
            unsigned hi[4], lo[4];
#pragma unroll
            for (int p = 0; p < 4; p++) {
                int j = mt*16 + (l>>2) + (p&1)*8;
                int k = kt*16 + (l&3)*2 + ((p>>1)&1)*8;
                const float* src = W_out + (size_t)j*256 + k;
                float r0, r1;
                hi[p] = pbf(src[0], src[1], &r0, &r1);
                lo[p] = pklo(r0, r1);
            }
            g_WOf_hi[(size_t)tl*32 + l] = make_uint4(hi[0],hi[1],hi[2],hi[3]);
            g_WOf_lo[(size_t)tl*32 + l] = make_uint4(lo[0],lo[1],lo[2],lo[3]);
        }
    } else {
        int gw = (b - 3976)*8 + wid;
        if (gw >= 8192) return;
        int kt = gw >> 9, n8 = gw & 511;
        int n = n8*8 + (l >> 2);
        int k0 = kt*16 + (l & 3)*2;
        const float* src = g_X + (size_t)n*256;
        float r0, r1, r2, r3;
        unsigned h0 = pbf(src[k0],   src[k0+1], &r0, &r1);
        unsigned h1 = pbf(src[k0+8], src[k0+9], &r2, &r3);
        g_Aaf_hi[(size_t)gw*32 + l] = ((ull)h1 << 32) | h0;
        g_Aaf_lo[(size_t)gw*32 + l] = ((ull)pklo(r2,r3) << 32) | pklo(r0,r1);
    }
}

// ---------------- activation fragments (standalone, for epilogue) ----------------
__global__ __launch_bounds__(256) void kPackA(const float* __restrict__ A)
{
    int gw = blockIdx.x*8 + (threadIdx.x >> 5);
    int l = threadIdx.x & 31;
    int kt = gw >> 9, n8 = gw & 511;
    int n = n8*8 + (l >> 2);
    int k0 = kt*16 + (l & 3)*2;
    const float* src = A + (size_t)n*256;
    float r0, r1, r2, r3;
    unsigned h0 = pbf(src[k0],   src[k0+1], &r0, &r1);
    unsigned h1 = pbf(src[k0+8], src[k0+9], &r2, &r3);
    g_Aaf_hi[(size_t)gw*32 + l] = ((ull)h1 << 32) | h0;
    g_Aaf_lo[(size_t)gw*32 + l] = ((ull)pklo(r2,r3) << 32) | pklo(r0,r1);
}

// ---------------- big mma GEMM ----------------
template<int MODE>
__global__ __launch_bounds__(256) void kMMAW(const uint4* __restrict__ Wh, const uint4* __restrict__ Wl,
                                             const float* __restrict__ bias1, const float* __restrict__ bias2,
                                             float* __restrict__ out, int MT)
{
    int wid = threadIdx.x >> 5, l = threadIdx.x & 31;
    int mt = blockIdx.x*8 + wid;
    if (mt >= MT) return;
    int by = blockIdx.y;
    float d[16][4];
#pragma unroll
    for (int i=0;i<16;i++)
#pragma unroll
        for (int j=0;j<4;j++) d[i][j] = 0.f;
    for (int kt = 0; kt < 16; kt++) {
        uint4 wh = __ldg(Wh + ((size_t)mt*16 + kt)*32 + l);
        uint4 wl = __ldg(Wl + ((size_t)mt*16 + kt)*32 + l);
#pragma unroll
        for (int n8 = 0; n8 < 16; n8++) {
            size_t bi = ((size_t)kt*512 + by*16 + n8)*32 + l;
            ull bh = __ldg(g_Aaf_hi + bi), bl = __ldg(g_Aaf_lo + bi);
            unsigned bh0=(unsigned)bh, bh1=(unsigned)(bh>>32);
            unsigned bl0=(unsigned)bl, bl1=(unsigned)(bl>>32);
            mma16816(d[n8], wh, bh0, bh1);
            mma16816(d[n8], wh, bl0, bl1);
            mma16816(d[n8], wl, bh0, bh1);
        }
    }
    int jr0 = mt*16 + (l >> 2), jr1 = jr0 + 8;
    float b0, b1;
    if (MODE == 0) {
        int j0 = (jr0 & 3)*1024 + (jr0 >> 2), j1 = (jr1 & 3)*1024 + (jr1 >> 2);
        b0 = bias1[j0] + bias2[j0];
        b1 = bias1[j1] + bias2[j1];
    } else {
        b0 = bias1[jr0]; b1 = bias1[jr1];
    }
#pragma unroll
    for (int n8 = 0; n8 < 16; n8++) {
        int r = by*128 + n8*8 + (l & 3)*2;
        int n0 = r & 31, t0 = r >> 5;
        if (MODE == 0) {
            *(float2*)&g_Xg2[((size_t)t0*G1 + jr0)*32 + n0] = make_float2(d[n8][0]+b0, d[n8][1]+b0);
            *(float2*)&g_Xg2[((size_t)t0*G1 + jr1)*32 + n0] = make_float2(d[n8][2]+b1, d[n8][3]+b1);
        } else {
            float* o0 = out + ((size_t)n0*LD + t0)*VV;
            float* o1 = out + ((size_t)(n0+1)*LD + t0)*VV;
            o0[jr0] = d[n8][0] + b0;  o1[jr0] = d[n8][1] + b0;
            o0[jr1] = d[n8][2] + b1;  o1[jr1] = d[n8][3] + b1;
        }
    }
}

// ---------------- persistent decoder ----------------
__global__ __launch_bounds__(256, 1) void kPersist(
    const float* __restrict__ key, const float* __restrict__ values,
    const int* __restrict__ elens,
    const float* __restrict__ b_ih2, const float* __restrict__ b_hh2)
{
    extern __shared__ float smem[];               // 32 KB
    __shared__ __align__(16) float sh2[128];
    __shared__ float es[512];
    __shared__ float red[256];

    int bid = blockIdx.x, tid = threadIdx.x;
    int wid = tid >> 5, w = tid & 31;
    int na = bid >> 2, q = bid & 3;               // attention group

    for (int t = 0; t < LD; t++) {
        // ===== Phase A: P1 ctx GEMM + reduce + cell1 =====
        {
            uint4* u4 = (uint4*)smem;
            for (int i = tid; i < 1024; i += 256)
                u4[i] = ldcg4((const uint4*)g_A + i);
            __syncthreads();
            int nt = w >> 3, jt = w & 7;
            const float* wp = g_Wt1 + (wid*16)*G1 + bid*32 + jt*4;
            const float* ap = smem + (wid*16)*32 + nt*8;
            ull acc[4][4];
#pragma unroll
            for (int i=0;i<4;i++)
#pragma unroll
                for (int j=0;j<4;j++) acc[i][j] = 0ull;
#pragma unroll
            for (int k = 0; k < 16; k++) {
                float4 wv = __ldg((const float4*)wp); wp += G1;
                const ull* a8 = (const ull*)ap; ap += 32;
                ull a0=a8[0], a1=a8[1], a2=a8[2], a3=a8[3];
                ull w0=pack2(wv.x), w1=pack2(wv.y), w2=pack2(wv.z), w3=pack2(wv.w);
                fma2(acc[0][0],w0,a0); fma2(acc[0][1],w0,a1); fma2(acc[0][2],w0,a2); fma2(acc[0][3],w0,a3);
                fma2(acc[1][0],w1,a0); fma2(acc[1][1],w1,a1); fma2(acc[1][2],w1,a2); fma2(acc[1][3],w1,a3);
                fma2(acc[2][0],w2,a0); fma2(acc[2][1],w2,a1); fma2(acc[2][2],w2,a2); fma2(acc[2][3],w2,a3);
                fma2(acc[3][0],w3,a0); fma2(acc[3][1],w3,a1); fma2(acc[3][2],w3,a2); fma2(acc[3][3],w3,a3);
            }
            __syncthreads();
#pragma unroll
            for (int jj=0;jj<4;jj++)
#pragma unroll
                for (int p=0;p<4;p++)
                    *(ull*)&smem[(wid*32 + jt*4+jj)*32 + nt*8 + p*2] = acc[jj][p];
            __syncthreads();
            int u_loc = tid >> 5, n = tid & 31;
            int u_glob = bid*8 + u_loc;
            float G[4];
#pragma unroll
            for (int g = 0; g < 4; g++) {
                int jp = u_glob*4 + g;
                float s = ldcgf(&g_Xg2[((size_t)t*G1 + jp)*32 + n]);
#pragma unroll
                for (int sp = 0; sp < 3; sp++) s += ldcgf(&g_hhp[((size_t)sp*G1 + jp)*32 + n]);
#pragma unroll
                for (int qq = 0; qq < 8; qq++) s += smem[(qq*32 + u_loc*4 + g)*32 + n];
                G[g] = s;
            }
            float i_ = sigm(G[0]), f_ = sigm(G[1]), gg = tanhf(G[2]), o_ = sigm(G[3]);
            float c = f_*g_c1[u_glob*32 + n] + i_*gg;
            g_c1[u_glob*32 + n] = c;
            float h = o_*tanhf(c);
            af_write(u_glob >> 4, n, u_glob & 15, h);
        }
        gbar();

        // ===== Phase B: P2 (blocks 0-31) || hh-GEMM t+1 (blocks 32-127) =====
        if (bid < NB) {
            float d[4][4];
#pragma unroll
            for (int i=0;i<4;i++)
#pragma unroll
                for (int j=0;j<4;j++) d[i][j]=0.f;
            const uint4* Ah = g_W2f_hi + ((size_t)bid*72 + wid*9)*32 + w;
            const uint4* Al = g_W2f_lo + ((size_t)bid*72 + wid*9)*32 + w;
            const ull* Bh = (const ull*)g_Af_hi;
            const ull* Bl = (const ull*)g_Af_lo;
            for (int kt = wid*9; kt < wid*9 + 9; kt++) {
                uint4 ah = ldcg4(Ah); Ah += 32;
                uint4 al = ldcg4(Al); Al += 32;
                int boff = kt*128 + w;
#pragma unroll
                for (int n8 = 0; n8 < 4; n8++) {
                    ull bh = ldcg8(Bh + boff + n8*32);
                    ull bl = ldcg8(Bl + boff + n8*32);
                    unsigned bh0=(unsigned)bh, bh1=(unsigned)(bh>>32);
                    unsigned bl0=(unsigned)bl, bl1=(unsigned)(bl>>32);
                    mma16816(d[n8], ah, bh0, bh1);
                    mma16816(d[n8], ah, bl0, bl1);
                    mma16816(d[n8], al, bh0, bh1);
                }
            }
            int jl0 = w >> 2, c0 = (w & 3)*2;
#pragma unroll
            for (int n8 = 0; n8 < 4; n8++) {
                *(float2*)&smem[wid*512 + jl0*32 + n8*8 + c0]     = make_float2(d[n8][0], d[n8][1]);
                *(float2*)&smem[wid*512 + (jl0+8)*32 + n8*8 + c0] = make_float2(d[n8][2], d[n8][3]);
            }
            __syncthreads();
            for (int o = tid; o < 512; o += 256) {
                int jl = o >> 5, n = o & 31;
                float s = 0.f;
#pragma unroll
                for (int qq = 0; qq < 8; qq++) s += smem[qq*512 + o];
                g_g2T[n*512 + bid*16 + jl] = s;
            }
            __syncthreads();
        } else if (t < LD-1) {
            int idx = bid - 32;
            int jc = idx / 3, ks3 = idx - jc*3;
            int kt0 = (ks3==0) ? 0 : ((ks3==1) ? 22 : 43);
            int nkt = (ks3==0) ? 22 : 21;
            int mt = jc*8 + wid;
            float d[4][4];
#pragma unroll
            for (int i=0;i<4;i++)
#pragma unroll
                for (int j=0;j<4;j++) d[i][j]=0.f;
            const uint4* Ah = g_W1f_hi + ((size_t)mt*64 + kt0)*32 + w;
            const uint4* Al = g_W1f_lo + ((size_t)mt*64 + kt0)*32 + w;
            const ull* Bh = (const ull*)g_Af_hi;
            const ull* Bl = (const ull*)g_Af_lo;
            for (int kt = kt0; kt < kt0 + nkt; kt++) {
                uint4 ah = ldcg4(Ah); Ah += 32;
                uint4 al = ldcg4(Al); Al += 32;
                int boff = kt*128 + w;
#pragma unroll
                for (int n8 = 0; n8 < 4; n8++) {
                    ull bh = ldcg8(Bh + boff + n8*32);
                    ull bl = ldcg8(Bl + boff + n8*32);
                    unsigned bh0=(unsigned)bh, bh1=(unsigned)(bh>>32);
                    unsigned bl0=(unsigned)bl, bl1=(unsigned)(bl>>32);
                    mma16816(d[n8], ah, bh0, bh1);
                    mma16816(d[n8], ah, bl0, bl1);
                    mma16816(d[n8], al, bh0, bh1);
                }
            }
            int r0 = mt*16 + (w >> 2);
            int c0 = (w & 3)*2;
#pragma unroll
            for (int n8 = 0; n8 < 4; n8++) {
                *(float2*)&g_hhp[((size_t)ks3*G1 + r0)*32 + n8*8 + c0]   = make_float2(d[n8][0], d[n8][1]);
                *(float2*)&g_hhp[((size_t)ks3*G1 + r0+8)*32 + n8*8 + c0] = make_float2(d[n8][2], d[n8][3]);
            }
        }
        gbar();

        // ===== Phase C: cell2 (redundant per group) + energy te-slice =====
        {
            if (tid < 128) {
                int u = tid;
                float4 gv;
                gv.x = ldcgf(&g_g2T[na*512 + u*4+0]);
                gv.y = ldcgf(&g_g2T[na*512 + u*4+1]);
                gv.z = ldcgf(&g_g2T[na*512 + u*4+2]);
                gv.w = ldcgf(&g_g2T[na*512 + u*4+3]);
                float i_ = sigm(gv.x + b_ih2[u]       + b_hh2[u]);
                float f_ = sigm(gv.y + b_ih2[128+u]   + b_hh2[128+u]);
                float gg = tanhf(gv.z + b_ih2[256+u]  + b_hh2[256+u]);
                float o_ = sigm(gv.w + b_ih2[384+u]   + b_hh2[384+u]);
                float c = f_*g_c2[(t&1)*4096 + na*128 + u] + i_*gg;
                float h = o_*tanhf(c);
                sh2[u] = h;
                if (q == 0) {
                    g_c2[((t+1)&1)*4096 + na*128 + u] = c;
                    af_write(64 + (u >> 4), na, u & 15, h);
                    g_h2ctx[((size_t)t*32 + na)*256 + u] = h;
                }
            }
            __syncthreads();
            int len = elens[na];
            float4 hv = ((const float4*)sh2)[w];
            int te0 = q*128 + wid*16;
            for (int b4 = 0; b4 < 16; b4 += 4) {
                float p[4];
#pragma unroll
                for (int i=0;i<4;i++) {
                    float4 kv = ((const float4*)&key[((size_t)na*TE + te0 + b4 + i)*KSZ])[w];
                    p[i] = kv.x*hv.x + kv.y*hv.y + kv.z*hv.z + kv.w*hv.w;
                }
#pragma unroll
                for (int sh = 16; sh > 0; sh >>= 1) {
#pragma unroll
                    for (int i=0;i<4;i++) p[i] += __shfl_xor_sync(0xffffffffu, p[i], sh);
                }
                if (w < 4) {
                    int te = te0 + b4 + w;
                    g_esG[na*512 + te] = (te >= len) ? -1.0e9f : p[w];
                }
            }
        }
        gbar();

        // ===== Phase D: softmax (redundant) + context v-slice =====
        {
            float e0 = ldcgf(&g_esG[na*512 + tid]);
            float e1 = ldcgf(&g_esG[na*512 + 256 + tid]);
            red[tid] = fmaxf(e0, e1);
            __syncthreads();
            for (int st = 128; st > 0; st >>= 1) {
                if (tid < st) red[tid] = fmaxf(red[tid], red[tid + st]);
                __syncthreads();
            }
            float mx = red[0];
            __syncthreads();
            float p0 = expf(e0 - mx), p1 = expf(e1 - mx);
            es[tid] = p0; es[tid + 256] = p1;
            red[tid] = p0 + p1;
            __syncthreads();
            for (int st = 128; st > 0; st >>= 1) {
                if (tid < st) red[tid] += red[tid + st];
                __syncthreads();
            }
            float inv = 1.0f / red[0];
            __syncthreads();
            // context: warp wid covers te [wid*64, wid*64+64), lane w owns v = q*32+w
            float acc = 0.f;
            const float* vp = values + ((size_t)na*TE + wid*64)*128 + q*32 + w;
#pragma unroll 8
            for (int te = 0; te < 64; te++) {
                acc += es[wid*64 + te] * __ldg(vp);
                vp += 128;
            }
            red[wid*32 + w] = acc;
            __syncthreads();
            if (tid < 32) {
                float s = 0.f;
#pragma unroll
                for (int g = 0; g < 8; g++) s += red[g*32 + tid];
                float ctx = s * inv;
                int v = q*32 + tid;
                g_A[v*32 + na] = ctx;
                g_h2ctx[((size_t)t*32 + na)*256 + 128 + v] = ctx;
            }
            __syncthreads();
        }
        gbar();
    }
}

// ---------------- launch ----------------
extern "C" void kernel_launch(void* const* d_in, const int* in_sizes, int n_in,
                              void* d_out, int out_size)
{
    const float* key    = (const float*)d_in[0];
    const float* values = (const float*)d_in[1];
    const int*   elens  = (const int*)  d_in[2];
    const int*   text   = (const int*)  d_in[3];
    const float* emb    = (const float*)d_in[4];
    const float* W_ih1  = (const float*)d_in[5];
    const float* W_hh1  = (const float*)d_in[6];
    const float* b_ih1  = (const float*)d_in[7];
    const float* b_hh1  = (const float*)d_in[8];
    const float* W_ih2  = (const float*)d_in[9];
    const float* W_hh2  = (const float*)d_in[10];
    const float* b_ih2  = (const float*)d_in[11];
    const float* b_hh2  = (const float*)d_in[12];
    const float* W_out  = (const float*)d_in[13];
    const float* b_out  = (const float*)d_in[14];
    float* out = (float*)d_out;

    cudaFuncSetAttribute(kPersist, cudaFuncAttributeMaxDynamicSharedMemorySize, 32768);

    kInit<<<LD*NB + 1856, 256>>>(text, emb, values);
    kPackAll<<<5000, 256>>>(W_ih1, W_hh1, W_ih2, W_hh2, W_out);

    uint4 *wxh, *wxl, *woh, *wol;
    cudaGetSymbolAddress((void**)&wxh, g_WXf_hi);
    cudaGetSymbolAddress((void**)&wxl, g_WXf_lo);
    cudaGetSymbolAddress((void**)&woh, g_WOf_hi);
    cudaGetSymbolAddress((void**)&wol, g_WOf_lo);
    kMMAW<0><<<dim3(32,32), 256>>>(wxh, wxl, b_ih1, b_hh1, (float*)0, 256);

    kPersist<<<NBLK, 256, 32768>>>(key, values, elens, b_ih2, b_hh2);

    float* gHC; cudaGetSymbolAddress((void**)&gHC, g_h2ctx);
    kPackA<<<1024, 256>>>(gHC);
    kMMAW<1><<<dim3(63,32), 256>>>(woh, wol, b_out, (const float*)0, out, 500);
}

// round 15
// speedup vs baseline: 2.8279x; 1.1824x over previous
#include <cuda_runtime.h>
#include <cuda_bf16.h>
#include <math.h>

#define NB 32
#define TE 512
#define LD 128
#define VV 8000
#define HH 1024
#define KSZ 128
#define G1 4096
#define KT 1152
#define NBLK 128
typedef unsigned long long ull;

__device__ __align__(16) float g_X[(LD*NB)*256];
__device__ __align__(16) float g_Xg2[(size_t)LD*G1*NB];
__device__ __align__(16) float g_Wt1[128*G1];       // ctx part k-major [k][j']
__device__ __align__(16) float g_A[128*NB];         // ctx fp32 [k][n]
__device__ __align__(16) float g_c1[HH*NB];
__device__ __align__(16) float g_c2[2*NB*KSZ];      // double buffered
__device__ __align__(16) float g_hhp[3*G1*NB];
__device__ __align__(16) float g_g2T[NB*512];
__device__ __align__(16) float g_esG[NB*512];
__device__ __align__(16) float g_h2ctx[(LD*NB)*256];
__device__ uint4 g_W1f_hi[524288], g_W1f_lo[524288];
__device__ uint4 g_W2f_hi[73728],  g_W2f_lo[73728];
__device__ unsigned g_Af_hi[18432], g_Af_lo[18432];
__device__ uint4 g_WXf_hi[131072], g_WXf_lo[131072];
__device__ uint4 g_WOf_hi[256000], g_WOf_lo[256000];
__device__ ull g_Aaf_hi[262144], g_Aaf_lo[262144];
// epoch barrier counters (monotonic; zeroed by kInit each launch)
__device__ unsigned g_grpA[8*32], g_grpB[4*32], g_grpC[32*32], g_grpD[8*32];
__device__ unsigned g_mstA = 0, g_mstB = 0, g_mstD = 0;

__device__ __forceinline__ float sigm(float x){ return 1.0f/(1.0f + expf(-x)); }
__device__ __forceinline__ unsigned atomAddRel(unsigned* p, unsigned v){
    unsigned r; asm volatile("atom.add.release.gpu.global.u32 %0, [%1], %2;"
                             : "=r"(r) : "l"(p), "r"(v) : "memory"); return r; }
__device__ __forceinline__ unsigned ldacq(const unsigned* p){
    unsigned v; asm volatile("ld.acquire.gpu.global.u32 %0, [%1];"
                             : "=r"(v) : "l"(p) : "memory"); return v; }

__device__ __forceinline__ void fma2(ull& d, ull a, ull b){
    asm("fma.rn.f32x2 %0, %1, %2, %0;" : "+l"(d) : "l"(a), "l"(b));
}
__device__ __forceinline__ ull pack2(float x){
    ull d; unsigned u = __float_as_uint(x);
    asm("mov.b64 %0, {%1, %1};" : "=l"(d) : "r"(u));
    return d;
}
__device__ __forceinline__ uint4 ldcg4(const uint4* p){
    uint4 v; asm("ld.global.cg.v4.u32 {%0,%1,%2,%3}, [%4];"
                 : "=r"(v.x),"=r"(v.y),"=r"(v.z),"=r"(v.w) : "l"(p)); return v; }
__device__ __forceinline__ ull ldcg8(const ull* p){
    ull v; asm("ld.global.cg.u64 %0, [%1];" : "=l"(v) : "l"(p)); return v; }
__device__ __forceinline__ float ldcgf(const float* p){
    float v; asm("ld.global.cg.f32 %0, [%1];" : "=f"(v) : "l"(p)); return v; }

__device__ __forceinline__ void mma16816(float* d, uint4 a, unsigned b0, unsigned b1){
    asm("mma.sync.aligned.m16n8k16.row.col.f32.bf16.bf16.f32 "
        "{%0,%1,%2,%3}, {%4,%5,%6,%7}, {%8,%9}, {%0,%1,%2,%3};"
        : "+f"(d[0]), "+f"(d[1]), "+f"(d[2]), "+f"(d[3])
        : "r"(a.x), "r"(a.y), "r"(a.z), "r"(a.w), "r"(b0), "r"(b1));
}
__device__ __forceinline__ unsigned pbf(float e0, float e1, float* r0, float* r1){
    __nv_bfloat16 h0 = __float2bfloat16(e0), h1 = __float2bfloat16(e1);
    *r0 = e0 - __bfloat162float(h0);
    *r1 = e1 - __bfloat162float(h1);
    return (unsigned)__bfloat16_as_ushort(h0) | ((unsigned)__bfloat16_as_ushort(h1) << 16);
}
__device__ __forceinline__ unsigned pklo(float a, float b){
    return (unsigned)__bfloat16_as_ushort(__float2bfloat16(a)) |
           ((unsigned)__bfloat16_as_ushort(__float2bfloat16(b)) << 16);
}
__device__ __forceinline__ void af_write(int ktA, int n, int kp, float v){
    __nv_bfloat16 bh = __float2bfloat16(v);
    __nv_bfloat16 bl = __float2bfloat16(v - __bfloat162float(bh));
    int n8 = n >> 3, np = n & 7;
    int lane = np*4 + ((kp & 7) >> 1);
    int reg = kp >> 3, half = kp & 1;
    size_t bi = ((((size_t)ktA*4 + n8)*32 + lane)*2 + reg)*2 + half;
    ((__nv_bfloat16*)g_Af_hi)[bi] = bh;
    ((__nv_bfloat16*)g_Af_lo)[bi] = bl;
}

// ---------------- init ----------------
__global__ __launch_bounds__(256) void kInit(const int* __restrict__ text,
                                             const float* __restrict__ emb,
                                             const float* __restrict__ values)
{
    int b = blockIdx.x, tid = threadIdx.x;
    if (b < LD*NB) {
        int t = b >> 5, n = b & 31;
        int idx = (t == 0) ? 1 : text[n*LD + (t-1)];
        g_X[b*256 + tid] = emb[idx*256 + tid];
    } else {
        int i = (b - LD*NB)*256 + tid;
        if      (i < 32768) g_c1[i] = 0.f;
        else if (i < 40960) g_c2[i - 32768] = 0.f;
        else if (i < 45056) { int u = i - 40960; int k = u >> 5, n = u & 31;
                              g_A[k*32 + n] = values[n*(TE*128) + k]; }
        else if (i < 438272) g_hhp[i - 45056] = 0.f;
        else {
            int z = i - 438272;
            if      (z < 18432) g_Af_hi[z] = 0u;
            else if (z < 36864) g_Af_lo[z - 18432] = 0u;
            else {
                int y = z - 36864;
                if      (y < 256)  g_grpA[y] = 0u;
                else if (y < 384)  g_grpB[y - 256] = 0u;
                else if (y < 1408) g_grpC[y - 384] = 0u;
                else if (y < 1664) g_grpD[y - 1408] = 0u;
                else if (y == 1664) g_mstA = 0u;
                else if (y == 1665) g_mstB = 0u;
                else if (y == 1666) g_mstD = 0u;
            }
        }
    }
}

// ---------------- all packing in one kernel ----------------
__global__ __launch_bounds__(256) void kPackAll(const float* __restrict__ W_ih1,
                                                const float* __restrict__ W_hh1,
                                                const float* __restrict__ W_ih2,
                                                const float* __restrict__ W_hh2,
                                                const float* __restrict__ W_out)
{
    __shared__ float s[32][129];
    int b = blockIdx.x, tid = threadIdx.x, wid = tid >> 5, l = tid & 31;
    if (b < 128) {
        int ub = b;
        int r = tid >> 3, c0 = (tid & 7) * 16;
        int g = r & 3, ul = r >> 2;
        int j = g*1024 + ub*8 + ul;
        const float* src = W_ih1 + j*384 + 256;
        for (int q = 0; q < 16; q += 4) {
            float4 v = *(const float4*)&src[c0+q];
            s[r][c0+q+0] = v.x; s[r][c0+q+1] = v.y;
            s[r][c0+q+2] = v.z; s[r][c0+q+3] = v.w;
        }
        __syncthreads();
        int rr = tid & 31, klg = tid >> 5;
        for (int kl = klg*16; kl < klg*16 + 16; kl++)
            g_Wt1[kl*G1 + ub*32 + rr] = s[rr][kl];
    } else if (b < 2464) {
        int bb = b - 128;
        if (bb < 2048) {
            int tile = bb*8 + wid;
            int mt = tile >> 6, kt = tile & 63;
            unsigned hi[4], lo[4];
#pragma unroll
            for (int p = 0; p < 4; p++) {
                int jp = mt*16 + (l>>2) + (p&1)*8;
                int u = jp >> 2, g = jp & 3;
                int k = kt*16 + (l&3)*2 + ((p>>1)&1)*8;
                const float* src = W_hh1 + (size_t)(g*1024+u)*1024 + k;
                float r0, r1;
                hi[p] = pbf(src[0], src[1], &r0, &r1);
                lo[p] = pklo(r0, r1);
            }
            g_W1f_hi[(size_t)tile*32 + l] = make_uint4(hi[0],hi[1],hi[2],hi[3]);
            g_W1f_lo[(size_t)tile*32 + l] = make_uint4(lo[0],lo[1],lo[2],lo[3]);
        } else {
            int tile = (bb - 2048)*8 + wid;
            if (tile >= 2304) return;
            int mt = tile / 72, kt = tile - mt*72;
            unsigned hi[4], lo[4];
#pragma unroll
            for (int p = 0; p < 4; p++) {
                int jp = mt*16 + (l>>2) + (p&1)*8;
                int u = jp >> 2, g = jp & 3;
                int k = kt*16 + (l&3)*2 + ((p>>1)&1)*8;
                const float* src = (k < 1024) ? (W_ih2 + (size_t)(g*128+u)*1024 + k)
                                              : (W_hh2 + (size_t)(g*128+u)*128 + (k - 1024));
                float r0, r1;
                hi[p] = pbf(src[0], src[1], &r0, &r1);
                lo[p] = pklo(r0, r1);
            }
            g_W2f_hi[(size_t)tile*32 + l] = make_uint4(hi[0],hi[1],hi[2],hi[3]);
            g_W2f_lo[(size_t)tile*32 + l] = make_uint4(lo[0],lo[1],lo[2],lo[3]);
        }
    } else if (b < 3976) {
        int tile = (b - 2464)*8 + wid;
        if (tile < 4096) {
            int mt = tile >> 4, kt = tile & 15;
            unsigned hi[4], lo[4];
#pragma unroll
            for (int p = 0; p < 4; p++) {
                int jp = mt*16 + (l>>2) + (p&1)*8;
                int j = (jp & 3)*1024 + (jp >> 2);
                int k = kt*16 + (l&3)*2 + ((p>>1)&1)*8;
                const float* src = W_ih1 + (size_t)j*384 + k;
                float r0, r1;
                hi[p] = pbf(src[0], src[1], &r0, &r1);
                lo[p] = pklo(r0, r1);
            }
            g_WXf_hi[(size_t)tile*32 + l] = make_uint4(hi[0],hi[1],hi[2],hi[3]);
            g_WXf_lo[(size_t)tile*32 + l] = make_uint4(lo[0],lo[1],lo[2],lo[3]);
        } else {
            int tl = tile - 4096;
            if (tl >= 8000) return;
            int mt = tl >> 4, kt = tl & 15;
            unsigned hi[4], lo[4];
#pragma unroll
            for (int p = 0; p < 4; p++) {
                int j = mt*16 + (l>>2) + (p&1)*8;
                int k = kt*16 + (l&3)*2 + ((p>>1)&1)*8;
                const float* src = W_out + (size_t)j*256 + k;
                float r0, r1;
                hi[p] = pbf(src[0], src[1], &r0, &r1);
                lo[p] = pklo(r0, r1);
            }
            g_WOf_hi[(size_t)tl*32 + l] = make_uint4(hi[0],hi[1],hi[2],hi[3]);
            g_WOf_lo[(size_t)tl*32 + l] = make_uint4(lo[0],lo[1],lo[2],lo[3]);
        }
    } else {
        int gw = (b - 3976)*8 + wid;
        if (gw >= 8192) return;
        int kt = gw >> 9, n8 = gw & 511;
        int n = n8*8 + (l >> 2);
        int k0 = kt*16 + (l & 3)*2;
        const float* src = g_X + (size_t)n*256;
        float r0, r1, r2, r3;
        unsigned h0 = pbf(src[k0],   src[k0+1], &r0, &r1);
        unsigned h1 = pbf(src[k0+8], src[k0+9], &r2, &r3);
        g_Aaf_hi[(size_t)gw*32 + l] = ((ull)h1 << 32) | h0;
        g_Aaf_lo[(size_t)gw*32 + l] = ((ull)pklo(r2,r3) << 32) | pklo(r0,r1);
    }
}

// ---------------- activation fragments (standalone, for epilogue) ----------------
__global__ __launch_bounds__(256) void kPackA(const float* __restrict__ A)
{
    int gw = blockIdx.x*8 + (threadIdx.x >> 5);
    int l = threadIdx.x & 31;
    int kt = gw >> 9, n8 = gw & 511;
    int n = n8*8 + (l >> 2);
    int k0 = kt*16 + (l & 3)*2;
    const float* src = A + (size_t)n*256;
    float r0, r1, r2, r3;
    unsigned h0 = pbf(src[k0],   src[k0+1], &r0, &r1);
    unsigned h1 = pbf(src[k0+8], src[k0+9], &r2, &r3);
    g_Aaf_hi[(size_t)gw*32 + l] = ((ull)h1 << 32) | h0;
    g_Aaf_lo[(size_t)gw*32 + l] = ((ull)pklo(r2,r3) << 32) | pklo(r0,r1);
}

// ---------------- big mma GEMM ----------------
template<int MODE>
__global__ __launch_bounds__(256) void kMMAW(const uint4* __restrict__ Wh, const uint4* __restrict__ Wl,
                                             const float* __restrict__ bias1, const float* __restrict__ bias2,
                                             float* __restrict__ out, int MT)
{
    int wid = threadIdx.x >> 5, l = threadIdx.x & 31;
    int mt = blockIdx.x*8 + wid;
    if (mt >= MT) return;
    int by = blockIdx.y;
    float d[16][4];
#pragma unroll
    for (int i=0;i<16;i++)
#pragma unroll
        for (int j=0;j<4;j++) d[i][j] = 0.f;
    for (int kt = 0; kt < 16; kt++) {
        uint4 wh = __ldg(Wh + ((size_t)mt*16 + kt)*32 + l);
        uint4 wl = __ldg(Wl + ((size_t)mt*16 + kt)*32 + l);
#pragma unroll
        for (int n8 = 0; n8 < 16; n8++) {
            size_t bi = ((size_t)kt*512 + by*16 + n8)*32 + l;
            ull bh = __ldg(g_Aaf_hi + bi), bl = __ldg(g_Aaf_lo + bi);
            unsigned bh0=(unsigned)bh, bh1=(unsigned)(bh>>32);
            unsigned bl0=(unsigned)bl, bl1=(unsigned)(bl>>32);
            mma16816(d[n8], wh, bh0, bh1);
            mma16816(d[n8], wh, bl0, bl1);
            mma16816(d[n8], wl, bh0, bh1);
        }
    }
    int jr0 = mt*16 + (l >> 2), jr1 = jr0 + 8;
    float b0, b1;
    if (MODE == 0) {
        int j0 = (jr0 & 3)*1024 + (jr0 >> 2), j1 = (jr1 & 3)*1024 + (jr1 >> 2);
        b0 = bias1[j0] + bias2[j0];
        b1 = bias1[j1] + bias2[j1];
    } else {
        b0 = bias1[jr0]; b1 = bias1[jr1];
    }
#pragma unroll
    for (int n8 = 0; n8 < 16; n8++) {
        int r = by*128 + n8*8 + (l & 3)*2;
        int n0 = r & 31, t0 = r >> 5;
        if (MODE == 0) {
            *(float2*)&g_Xg2[((size_t)t0*G1 + jr0)*32 + n0] = make_float2(d[n8][0]+b0, d[n8][1]+b0);
            *(float2*)&g_Xg2[((size_t)t0*G1 + jr1)*32 + n0] = make_float2(d[n8][2]+b1, d[n8][3]+b1);
        } else {
            float* o0 = out + ((size_t)n0*LD + t0)*VV;
            float* o1 = out + ((size_t)(n0+1)*LD + t0)*VV;
            o0[jr0] = d[n8][0] + b0;  o1[jr0] = d[n8][1] + b0;
            o0[jr1] = d[n8][2] + b1;  o1[jr1] = d[n8][3] + b1;
        }
    }
}

// ---------------- persistent decoder ----------------
__global__ __launch_bounds__(256, 1) void kPersist(
    const float* __restrict__ key, const float* __restrict__ values,
    const int* __restrict__ elens,
    const float* __restrict__ b_ih2, const float* __restrict__ b_hh2)
{
    extern __shared__ float smem[];               // 32 KB
    __shared__ __align__(16) float sh2[128];
    __shared__ float es[512];
    __shared__ float red[256];

    int bid = blockIdx.x, tid = threadIdx.x;
    int wid = tid >> 5, w = tid & 31;
    int na = bid >> 2, q = bid & 3;               // attention group

    for (int t = 0; t < LD; t++) {
        unsigned t1 = (unsigned)(t + 1);
        // ===== Phase A: P1 ctx GEMM + reduce + cell1 =====
        {
            uint4* u4 = (uint4*)smem;
            for (int i = tid; i < 1024; i += 256)
                u4[i] = ldcg4((const uint4*)g_A + i);
            __syncthreads();
            int nt = w >> 3, jt = w & 7;
            const float* wp = g_Wt1 + (wid*16)*G1 + bid*32 + jt*4;
            const float* ap = smem + (wid*16)*32 + nt*8;
            ull acc[4][4];
#pragma unroll
            for (int i=0;i<4;i++)
#pragma unroll
                for (int j=0;j<4;j++) acc[i][j] = 0ull;
#pragma unroll
            for (int k = 0; k < 16; k++) {
                float4 wv = __ldg((const float4*)wp); wp += G1;
                const ull* a8 = (const ull*)ap; ap += 32;
                ull a0=a8[0], a1=a8[1], a2=a8[2], a3=a8[3];
                ull w0=pack2(wv.x), w1=pack2(wv.y), w2=pack2(wv.z), w3=pack2(wv.w);
                fma2(acc[0][0],w0,a0); fma2(acc[0][1],w0,a1); fma2(acc[0][2],w0,a2); fma2(acc[0][3],w0,a3);
                fma2(acc[1][0],w1,a0); fma2(acc[1][1],w1,a1); fma2(acc[1][2],w1,a2); fma2(acc[1][3],w1,a3);
                fma2(acc[2][0],w2,a0); fma2(acc[2][1],w2,a1); fma2(acc[2][2],w2,a2); fma2(acc[2][3],w2,a3);
                fma2(acc[3][0],w3,a0); fma2(acc[3][1],w3,a1); fma2(acc[3][2],w3,a2); fma2(acc[3][3],w3,a3);
            }
            __syncthreads();
#pragma unroll
            for (int jj=0;jj<4;jj++)
#pragma unroll
                for (int p=0;p<4;p++)
                    *(ull*)&smem[(wid*32 + jt*4+jj)*32 + nt*8 + p*2] = acc[jj][p];
            __syncthreads();
            int u_loc = tid >> 5, n = tid & 31;
            int u_glob = bid*8 + u_loc;
            float G[4];
#pragma unroll
            for (int g = 0; g < 4; g++) {
                int jp = u_glob*4 + g;
                float s = ldcgf(&g_Xg2[((size_t)t*G1 + jp)*32 + n]);
#pragma unroll
                for (int sp = 0; sp < 3; sp++) s += ldcgf(&g_hhp[((size_t)sp*G1 + jp)*32 + n]);
#pragma unroll
                for (int qq = 0; qq < 8; qq++) s += smem[(qq*32 + u_loc*4 + g)*32 + n];
                G[g] = s;
            }
            float i_ = sigm(G[0]), f_ = sigm(G[1]), gg = tanhf(G[2]), o_ = sigm(G[3]);
            float c = f_*g_c1[u_glob*32 + n] + i_*gg;
            g_c1[u_glob*32 + n] = c;
            float h = o_*tanhf(c);
            af_write(u_glob >> 4, n, u_glob & 15, h);
        }
        // full tree barrier A
        __syncthreads();
        if (tid == 0) {
            unsigned old = atomAddRel(&g_grpA[(bid & 7)*32], 1u);
            if (old == 16u*t1 - 1u) atomAddRel(&g_mstA, 1u);
            while ((int)(ldacq(&g_mstA) - 8u*t1) < 0) __nanosleep(32);
        }
        __syncthreads();

        // ===== Phase B: P2 (blocks 0-31) || hh-GEMM t+1 (blocks 32-127) =====
        if (bid < NB) {
            float d[4][4];
#pragma unroll
            for (int i=0;i<4;i++)
#pragma unroll
                for (int j=0;j<4;j++) d[i][j]=0.f;
            const uint4* Ah = g_W2f_hi + ((size_t)bid*72 + wid*9)*32 + w;
            const uint4* Al = g_W2f_lo + ((size_t)bid*72 + wid*9)*32 + w;
            const ull* Bh = (const ull*)g_Af_hi;
            const ull* Bl = (const ull*)g_Af_lo;
            for (int kt = wid*9; kt < wid*9 + 9; kt++) {
                uint4 ah = ldcg4(Ah); Ah += 32;
                uint4 al = ldcg4(Al); Al += 32;
                int boff = kt*128 + w;
#pragma unroll
                for (int n8 = 0; n8 < 4; n8++) {
                    ull bh = ldcg8(Bh + boff + n8*32);
                    ull bl = ldcg8(Bl + boff + n8*32);
                    unsigned bh0=(unsigned)bh, bh1=(unsigned)(bh>>32);
                    unsigned bl0=(unsigned)bl, bl1=(unsigned)(bl>>32);
                    mma16816(d[n8], ah, bh0, bh1);
                    mma16816(d[n8], ah, bl0, bl1);
                    mma16816(d[n8], al, bh0, bh1);
                }
            }
            int jl0 = w >> 2, c0 = (w & 3)*2;
#pragma unroll
            for (int n8 = 0; n8 < 4; n8++) {
                *(float2*)&smem[wid*512 + jl0*32 + n8*8 + c0]     = make_float2(d[n8][0], d[n8][1]);
                *(float2*)&smem[wid*512 + (jl0+8)*32 + n8*8 + c0] = make_float2(d[n8][2], d[n8][3]);
            }
            __syncthreads();
            for (int o = tid; o < 512; o += 256) {
                int jl = o >> 5, n = o & 31;
                float s = 0.f;
#pragma unroll
                for (int qq = 0; qq < 8; qq++) s += smem[qq*512 + o];
                g_g2T[n*512 + bid*16 + jl] = s;
            }
            __syncthreads();
            if (tid == 0) {
                unsigned old = atomAddRel(&g_grpB[(bid & 3)*32], 1u);
                if (old == 8u*t1 - 1u) atomAddRel(&g_mstB, 1u);
            }
        } else if (t < LD-1) {
            int idx = bid - 32;
            int jc = idx / 3, ks3 = idx - jc*3;
            int kt0 = (ks3==0) ? 0 : ((ks3==1) ? 22 : 43);
            int nkt = (ks3==0) ? 22 : 21;
            int mt = jc*8 + wid;
            float d[4][4];
#pragma unroll
            for (int i=0;i<4;i++)
#pragma unroll
                for (int j=0;j<4;j++) d[i][j]=0.f;
            const uint4* Ah = g_W1f_hi + ((size_t)mt*64 + kt0)*32 + w;
            const uint4* Al = g_W1f_lo + ((size_t)mt*64 + kt0)*32 + w;
            const ull* Bh = (const ull*)g_Af_hi;
            const ull* Bl = (const ull*)g_Af_lo;
            for (int kt = kt0; kt < kt0 + nkt; kt++) {
                uint4 ah = ldcg4(Ah); Ah += 32;
                uint4 al = ldcg4(Al); Al += 32;
                int boff = kt*128 + w;
#pragma unroll
                for (int n8 = 0; n8 < 4; n8++) {
                    ull bh = ldcg8(Bh + boff + n8*32);
                    ull bl = ldcg8(Bl + boff + n8*32);
                    unsigned bh0=(unsigned)bh, bh1=(unsigned)(bh>>32);
                    unsigned bl0=(unsigned)bl, bl1=(unsigned)(bl>>32);
                    mma16816(d[n8], ah, bh0, bh1);
                    mma16816(d[n8], ah, bl0, bl1);
                    mma16816(d[n8], al, bh0, bh1);
                }
            }
            int r0 = mt*16 + (w >> 2);
            int c0 = (w & 3)*2;
#pragma unroll
            for (int n8 = 0; n8 < 4; n8++) {
                *(float2*)&g_hhp[((size_t)ks3*G1 + r0)*32 + n8*8 + c0]   = make_float2(d[n8][0], d[n8][1]);
                *(float2*)&g_hhp[((size_t)ks3*G1 + r0+8)*32 + n8*8 + c0] = make_float2(d[n8][2], d[n8][3]);
            }
        }
        // wait for P2 producers (semaphore, one-sided)
        if (tid == 0) {
            while ((int)(ldacq(&g_mstB) - 4u*t1) < 0) __nanosleep(32);
        }
        __syncthreads();

        // ===== Phase C: cell2 (redundant per group) + energy te-slice =====
        {
            if (tid < 128) {
                int u = tid;
                float4 gv;
                gv.x = ldcgf(&g_g2T[na*512 + u*4+0]);
                gv.y = ldcgf(&g_g2T[na*512 + u*4+1]);
                gv.z = ldcgf(&g_g2T[na*512 + u*4+2]);
                gv.w = ldcgf(&g_g2T[na*512 + u*4+3]);
                float i_ = sigm(gv.x + b_ih2[u]       + b_hh2[u]);
                float f_ = sigm(gv.y + b_ih2[128+u]   + b_hh2[128+u]);
                float gg = tanhf(gv.z + b_ih2[256+u]  + b_hh2[256+u]);
                float o_ = sigm(gv.w + b_ih2[384+u]   + b_hh2[384+u]);
                float c = f_*ldcgf(&g_c2[(t&1)*4096 + na*128 + u]) + i_*gg;
                float h = o_*tanhf(c);
                sh2[u] = h;
                if (q == 0) {
                    g_c2[((t+1)&1)*4096 + na*128 + u] = c;
                    af_write(64 + (u >> 4), na, u & 15, h);
                    g_h2ctx[((size_t)t*32 + na)*256 + u] = h;
                }
            }
            __syncthreads();
            int len = elens[na];
            float4 hv = ((const float4*)sh2)[w];
            int te0 = q*128 + wid*16;
            for (int b4 = 0; b4 < 16; b4 += 4) {
                float p[4];
#pragma unroll
                for (int i=0;i<4;i++) {
                    float4 kv = ((const float4*)&key[((size_t)na*TE + te0 + b4 + i)*KSZ])[w];
                    p[i] = kv.x*hv.x + kv.y*hv.y + kv.z*hv.z + kv.w*hv.w;
                }
#pragma unroll
                for (int sh = 16; sh > 0; sh >>= 1) {
#pragma unroll
                    for (int i=0;i<4;i++) p[i] += __shfl_xor_sync(0xffffffffu, p[i], sh);
                }
                if (w < 4) {
                    int te = te0 + b4 + w;
                    g_esG[na*512 + te] = (te >= len) ? -1.0e9f : p[w];
                }
            }
        }
        // per-na group barrier (4 blocks)
        __syncthreads();
        if (tid == 0) {
            atomAddRel(&g_grpC[na*32], 1u);
            while ((int)(ldacq(&g_grpC[na*32]) - 4u*t1) < 0) __nanosleep(32);
        }
        __syncthreads();

        // ===== Phase D: softmax (redundant) + context v-slice =====
        {
            float e0 = ldcgf(&g_esG[na*512 + tid]);
            float e1 = ldcgf(&g_esG[na*512 + 256 + tid]);
            red[tid] = fmaxf(e0, e1);
            __syncthreads();
            for (int st = 128; st > 0; st >>= 1) {
                if (tid < st) red[tid] = fmaxf(red[tid], red[tid + st]);
                __syncthreads();
            }
            float mx = red[0];
            __syncthreads();
            float p0 = expf(e0 - mx), p1 = expf(e1 - mx);
            es[tid] = p0; es[tid + 256] = p1;
            red[tid] = p0 + p1;
            __syncthreads();
            for (int st = 128; st > 0; st >>= 1) {
                if (tid < st) red[tid] += red[tid + st];
                __syncthreads();
            }
            float inv = 1.0f / red[0];
            __syncthreads();
            float acc = 0.f;
            const float* vp = values + ((size_t)na*TE + wid*64)*128 + q*32 + w;
#pragma unroll 8
            for (int te = 0; te < 64; te++) {
                acc += es[wid*64 + te] * __ldg(vp);
                vp += 128;
            }
            red[wid*32 + w] = acc;
            __syncthreads();
            if (tid < 32) {
                float s = 0.f;
#pragma unroll
                for (int g = 0; g < 8; g++) s += red[g*32 + tid];
                float ctx = s * inv;
                int v = q*32 + tid;
                g_A[v*32 + na] = ctx;
                g_h2ctx[((size_t)t*32 + na)*256 + 128 + v] = ctx;
            }
        }
        // full tree barrier D
        __syncthreads();
        if (tid == 0) {
            unsigned old = atomAddRel(&g_grpD[(bid & 7)*32], 1u);
            if (old == 16u*t1 - 1u) atomAddRel(&g_mstD, 1u);
            while ((int)(ldacq(&g_mstD) - 8u*t1) < 0) __nanosleep(32);
        }
        __syncthreads();
    }
}

// ---------------- launch ----------------
extern "C" void kernel_launch(void* const* d_in, const int* in_sizes, int n_in,
                              void* d_out, int out_size)
{
    const float* key    = (const float*)d_in[0];
    const float* values = (const float*)d_in[1];
    const int*   elens  = (const int*)  d_in[2];
    const int*   text   = (const int*)  d_in[3];
    const float* emb    = (const float*)d_in[4];
    const float* W_ih1  = (const float*)d_in[5];
    const float* W_hh1  = (const float*)d_in[6];
    const float* b_ih1  = (const float*)d_in[7];
    const float* b_hh1  = (const float*)d_in[8];
    const float* W_ih2  = (const float*)d_in[9];
    const float* W_hh2  = (const float*)d_in[10];
    const float* b_ih2  = (const float*)d_in[11];
    const float* b_hh2  = (const float*)d_in[12];
    const float* W_out  = (const float*)d_in[13];
    const float* b_out  = (const float*)d_in[14];
    float* out = (float*)d_out;

    cudaFuncSetAttribute(kPersist, cudaFuncAttributeMaxDynamicSharedMemorySize, 32768);

    kInit<<<LD*NB + 1872, 256>>>(text, emb, values);
    kPackAll<<<5000, 256>>>(W_ih1, W_hh1, W_ih2, W_hh2, W_out);

    uint4 *wxh, *wxl, *woh, *wol;
    cudaGetSymbolAddress((void**)&wxh, g_WXf_hi);
    cudaGetSymbolAddress((void**)&wxl, g_WXf_lo);
    cudaGetSymbolAddress((void**)&woh, g_WOf_hi);
    cudaGetSymbolAddress((void**)&wol, g_WOf_lo);
    kMMAW<0><<<dim3(32,32), 256>>>(wxh, wxl, b_ih1, b_hh1, (float*)0, 256);

    kPersist<<<NBLK, 256, 32768>>>(key, values, elens, b_ih2, b_hh2);

    float* gHC; cudaGetSymbolAddress((void**)&gHC, g_h2ctx);
    kPackA<<<1024, 256>>>(gHC);
    kMMAW<1><<<dim3(63,32), 256>>>(woh, wol, b_out, (const float*)0, out, 500);
}